// round 1
// baseline (speedup 1.0000x reference)
#include <cuda_runtime.h>

// Problem constants
// B=8, C=128, IC=64, H=W=64, N=4096, M=1024 (pooled 32x32)

__device__ float g_wtp[132];            // [0..127] folded wt'=w5[:64]^T w3, [128] = w5[:64].b3
__device__ float g_bnA[128], g_bnB[128];
__device__ float g_t[8][4096];
__device__ float g_p[8][1024];
__device__ float g_xg[8][1024][64];
__device__ float g_psort[8][1024];
__device__ int   g_perm[8][1024];
__device__ float g_S1[8][1025][64];
__device__ float g_S2[8][1025][64];
__device__ float g_cs1[8][16][64];
__device__ float g_cs2[8][16][64];

// ---------------------------------------------------------------------------
// K0: fold weights + BN constants
// ---------------------------------------------------------------------------
__global__ void k0_prep(const float* __restrict__ w3, const float* __restrict__ b3,
                        const float* __restrict__ w5, const float* __restrict__ b2,
                        const float* __restrict__ bg, const float* __restrict__ bb,
                        const float* __restrict__ bm, const float* __restrict__ bv) {
    int c = threadIdx.x;  // 0..127
    float acc = 0.f;
    #pragma unroll 16
    for (int i = 0; i < 64; i++) acc = fmaf(w5[i], w3[i * 128 + c], acc);
    g_wtp[c] = acc;
    if (c == 0) {
        float s = 0.f;
        for (int i = 0; i < 64; i++) s = fmaf(w5[i], b3[i], s);
        g_wtp[128] = s;
    }
    float inv = rsqrtf(bv[c] + 1e-5f);
    float al  = bg[c] * inv;
    g_bnA[c] = al;
    g_bnB[c] = (b2[c] - bm[c]) * al + bb[c];
}

// ---------------------------------------------------------------------------
// K1: fused conv1+conv4 GEMM (128x128 per pooled row), maxpool via shfl,
//     produces g_xg, g_p, and the folded scalar t per pixel.
// grid (32 pooled-rows, 8 batch), 256 threads, dyn smem ~133 KB
// ---------------------------------------------------------------------------
__global__ void __launch_bounds__(256, 1)
k1_conv(const float* __restrict__ x,
        const float* __restrict__ w1, const float* __restrict__ b1,
        const float* __restrict__ w4, const float* __restrict__ b4,
        const float* __restrict__ w5) {
    extern __shared__ float sm[];
    float* sW    = sm;              // 128 oc x 128 c
    float* sX    = sm + 16384;      // 128 c  x 128 px
    float* sBias = sX + 16384;      // 128
    float* sWp   = sBias + 128;     // 64
    float* sWtp  = sWp + 64;        // 132
    float* sPred = sWtp + 132;      // 8 x 32

    const int tid = threadIdx.x;
    const int pr  = blockIdx.x;     // pooled row 0..31
    const int b   = blockIdx.y;

    // load weights [oc][c] (oc<64: w1, oc>=64: w4)
    const float4* w1v = (const float4*)w1;
    const float4* w4v = (const float4*)w4;
    #pragma unroll
    for (int k = 0; k < 16; k++) {
        int v  = tid + k * 256;
        int oc = v >> 5, c4 = v & 31;
        ((float4*)sW)[v] = (oc < 64) ? w1v[oc * 32 + c4] : w4v[(oc - 64) * 32 + c4];
    }
    // load x tile: 128 channels x 2 image rows (2*pr, 2*pr+1)
    const float4* xv = (const float4*)x;
    #pragma unroll
    for (int k = 0; k < 16; k++) {
        int v   = tid + k * 256;
        int rr  = v >> 4, c4 = v & 15;
        int c   = rr >> 1, r01 = rr & 1;
        ((float4*)sX)[c * 32 + r01 * 16 + c4] =
            xv[((b * 128 + c) * 64 + (2 * pr + r01)) * 16 + c4];
    }
    if (tid < 128) sBias[tid] = (tid < 64) ? b1[tid] : b4[tid - 64];
    if (tid < 64)  sWp[tid]   = w5[64 + tid];
    if (tid < 129) sWtp[tid]  = g_wtp[tid];
    __syncthreads();

    const int tx = tid & 15;   // px tile: tx*8 .. tx*8+7
    const int ty = tid >> 4;   // oc tile: ty*8 .. ty*8+7

    float acc[8][8];
    #pragma unroll
    for (int u = 0; u < 8; u++)
        #pragma unroll
        for (int v = 0; v < 8; v++) acc[u][v] = 0.f;

    const float* xp  = sX + tx * 8;
    const float* wr  = sW + ty * 8 * 128;
    #pragma unroll 4
    for (int c = 0; c < 128; c++) {
        float4 xa = *(const float4*)(xp + c * 128);
        float4 xb = *(const float4*)(xp + c * 128 + 4);
        float xr[8] = {xa.x, xa.y, xa.z, xa.w, xb.x, xb.y, xb.z, xb.w};
        #pragma unroll
        for (int u = 0; u < 8; u++) {
            float wv = wr[u * 128 + c];
            #pragma unroll
            for (int v = 0; v < 8; v++) acc[u][v] = fmaf(wv, xr[v], acc[u][v]);
        }
    }

    // t (folded conv3 dot): one pixel per thread for tid<128
    if (tid < 128) {
        float a = sWtp[128];
        const float* xc = sX + tid;
        #pragma unroll 8
        for (int c = 0; c < 128; c++) a = fmaf(sWtp[c], xc[c * 128], a);
        int n = (2 * pr + (tid >> 6)) * 64 + (tid & 63);
        g_t[b][n] = a;
    }

    // maxpool: horizontal in-register, vertical via shfl_xor(8) (tx <-> tx+8)
    float pl[8][4];
    #pragma unroll
    for (int u = 0; u < 8; u++)
        #pragma unroll
        for (int q = 0; q < 4; q++) {
            float hm = fmaxf(acc[u][2 * q], acc[u][2 * q + 1]);
            float ot = __shfl_xor_sync(0xffffffffu, hm, 8);
            pl[u][q] = fmaxf(hm, ot);
        }

    if (tx < 8) {
        if (ty < 8) {  // xg path (conv1 channels)
            float bbv[8];
            #pragma unroll
            for (int u = 0; u < 8; u++) bbv[u] = sBias[ty * 8 + u];
            int mb = pr * 32 + tx * 4;
            #pragma unroll
            for (int q = 0; q < 4; q++) {
                float4 lo = make_float4(pl[0][q] + bbv[0], pl[1][q] + bbv[1],
                                        pl[2][q] + bbv[2], pl[3][q] + bbv[3]);
                float4 hi = make_float4(pl[4][q] + bbv[4], pl[5][q] + bbv[5],
                                        pl[6][q] + bbv[6], pl[7][q] + bbv[7]);
                float* dst = &g_xg[b][mb + q][ty * 8];
                *(float4*)dst       = lo;
                *(float4*)(dst + 4) = hi;
            }
        } else {       // p path (conv4 channels dotted with wp)
            int g = ty - 8;
            #pragma unroll
            for (int q = 0; q < 4; q++) {
                float part = 0.f;
                #pragma unroll
                for (int u = 0; u < 8; u++)
                    part = fmaf(sWp[g * 8 + u], pl[u][q] + sBias[64 + g * 8 + u], part);
                sPred[g * 32 + tx * 4 + q] = part;
            }
        }
    }
    __syncthreads();
    if (tid < 32) {
        float pv = 0.f;
        #pragma unroll
        for (int g = 0; g < 8; g++) pv += sPred[g * 32 + tid];
        g_p[b][pr * 32 + tid] = pv;
    }
}

// ---------------------------------------------------------------------------
// K2a: bitonic sort of p per batch (ascending), keep permutation
// ---------------------------------------------------------------------------
__global__ void __launch_bounds__(1024) k2_sort() {
    __shared__ float sv[1024];
    __shared__ int   si[1024];
    int b = blockIdx.x, tid = threadIdx.x;
    sv[tid] = g_p[b][tid];
    si[tid] = tid;
    __syncthreads();
    for (int k = 2; k <= 1024; k <<= 1)
        for (int j = k >> 1; j > 0; j >>= 1) {
            int ixj = tid ^ j;
            if (ixj > tid) {
                float a = sv[tid], c = sv[ixj];
                bool up = (tid & k) == 0;
                if (up ? (a > c) : (a < c)) {
                    sv[tid] = c; sv[ixj] = a;
                    int t = si[tid]; si[tid] = si[ixj]; si[ixj] = t;
                }
            }
            __syncthreads();
        }
    g_psort[b][tid] = sv[tid];
    g_perm[b][tid]  = si[tid];
}

// ---------------------------------------------------------------------------
// K2b: per-chunk local suffix sums of xg (and p*xg) along sorted order
// grid (16 chunks, 8 batch), 64 threads (one per channel)
// ---------------------------------------------------------------------------
__global__ void k2_suffix_local() {
    int b = blockIdx.y, q = blockIdx.x, i = threadIdx.x;
    float a1 = 0.f, a2 = 0.f;
    #pragma unroll 4
    for (int jj = 63; jj >= 0; jj--) {
        int   j  = q * 64 + jj;
        int   m  = g_perm[b][j];
        float pv = g_psort[b][j];
        float xvv = g_xg[b][m][i];
        a1 += xvv;
        a2 = fmaf(pv, xvv, a2);
        g_S1[b][j][i] = a1;
        g_S2[b][j][i] = a2;
    }
    g_cs1[b][q][i] = a1;
    g_cs2[b][q][i] = a2;
    if (q == 0) { g_S1[b][1024][i] = 0.f; g_S2[b][1024][i] = 0.f; }
}

// K2c: add tail-of-later-chunks offsets
__global__ void k2_suffix_fix() {
    int b = blockIdx.y, q = blockIdx.x, i = threadIdx.x;
    if (q == 15) return;
    float t1 = 0.f, t2 = 0.f;
    for (int q2 = q + 1; q2 < 16; q2++) { t1 += g_cs1[b][q2][i]; t2 += g_cs2[b][q2][i]; }
    #pragma unroll 4
    for (int jj = 0; jj < 64; jj++) {
        int j = q * 64 + jj;
        g_S1[b][j][i] += t1;
        g_S2[b][j][i] += t2;
    }
}

// ---------------------------------------------------------------------------
// K3: per (b, 64-pixel tile): binary search k_n, build y (64n x 64i),
//     conv2 GEMM + BN + residual, write output.
// grid (64 tiles, 8 batch), 256 threads, dyn smem ~55 KB
// ---------------------------------------------------------------------------
__global__ void __launch_bounds__(256)
k3_out(const float* __restrict__ x, const float* __restrict__ w2,
       float* __restrict__ out) {
    extern __shared__ float sm[];
    float* sW2 = sm;              // 128 co x 64 i
    float* sYT = sW2 + 8192;      // 64 i x 68 (padded) n
    float* sPs = sYT + 64 * 68;   // 1024
    float* sT  = sPs + 1024;      // 64
    float* sA  = sT + 64;         // 128
    float* sB  = sA + 128;        // 128
    int*   sK  = (int*)(sB + 128);// 64

    int tid = threadIdx.x;
    int tile = blockIdx.x, b = blockIdx.y;
    int n0 = tile * 64;

    const float4* w2v = (const float4*)w2;
    #pragma unroll
    for (int k = 0; k < 8; k++) ((float4*)sW2)[tid + k * 256] = w2v[tid + k * 256];
    #pragma unroll
    for (int k = 0; k < 4; k++) sPs[tid + k * 256] = g_psort[b][tid + k * 256];
    if (tid < 64)  sT[tid] = g_t[b][n0 + tid];
    if (tid < 128) { sA[tid] = g_bnA[tid]; sB[tid] = g_bnB[tid]; }
    __syncthreads();

    if (tid < 64) {
        float key = -sT[tid];
        int lo = 0, hi = 1024;
        while (lo < hi) { int mid = (lo + hi) >> 1; if (sPs[mid] > key) hi = mid; else lo = mid + 1; }
        sK[tid] = lo;
    }
    __syncthreads();

    {   // y[n][i] = (t_n*S1[k][i] + S2[k][i]) / 1024, stored transposed [i][n]
        int iv = tid & 63, ng = tid >> 6;
        #pragma unroll 4
        for (int w = 0; w < 16; w++) {
            int n = ng * 16 + w;
            int k = sK[n];
            float t  = sT[n];
            float s1 = g_S1[b][k][iv];
            float s2 = g_S2[b][k][iv];
            sYT[iv * 68 + n] = fmaf(t, s1, s2) * (1.0f / 1024.0f);
        }
    }
    __syncthreads();

    int tx = tid & 15, ty = tid >> 4;
    float acc[8][4];
    #pragma unroll
    for (int u = 0; u < 8; u++)
        #pragma unroll
        for (int v = 0; v < 4; v++) acc[u][v] = 0.f;

    #pragma unroll 4
    for (int i = 0; i < 64; i++) {
        float4 yv = *(const float4*)(sYT + i * 68 + tx * 4);
        #pragma unroll
        for (int u = 0; u < 8; u++) {
            float wv = sW2[(ty * 8 + u) * 64 + i];
            acc[u][0] = fmaf(wv, yv.x, acc[u][0]);
            acc[u][1] = fmaf(wv, yv.y, acc[u][1]);
            acc[u][2] = fmaf(wv, yv.z, acc[u][2]);
            acc[u][3] = fmaf(wv, yv.w, acc[u][3]);
        }
    }

    #pragma unroll
    for (int u = 0; u < 8; u++) {
        int oc = ty * 8 + u;
        long idx = ((long)(b * 128 + oc)) * 4096 + n0 + tx * 4;
        float4 xr = *(const float4*)(x + idx);
        float a = sA[oc], bv = sB[oc];
        float4 o;
        o.x = fmaf(acc[u][0], a, bv) + xr.x;
        o.y = fmaf(acc[u][1], a, bv) + xr.y;
        o.z = fmaf(acc[u][2], a, bv) + xr.z;
        o.w = fmaf(acc[u][3], a, bv) + xr.w;
        *((float4*)(out + idx)) = o;
    }
}

// ---------------------------------------------------------------------------
extern "C" void kernel_launch(void* const* d_in, const int* in_sizes, int n_in,
                              void* d_out, int out_size) {
    const float* x  = (const float*)d_in[0];
    const float* w1 = (const float*)d_in[1];
    const float* b1 = (const float*)d_in[2];
    const float* w3 = (const float*)d_in[3];
    const float* b3 = (const float*)d_in[4];
    const float* w4 = (const float*)d_in[5];
    const float* b4 = (const float*)d_in[6];
    const float* w5 = (const float*)d_in[7];
    const float* w2 = (const float*)d_in[8];
    const float* b2 = (const float*)d_in[9];
    const float* bg = (const float*)d_in[10];
    const float* bb = (const float*)d_in[11];
    const float* bm = (const float*)d_in[12];
    const float* bv = (const float*)d_in[13];
    float* out = (float*)d_out;

    static_assert(sizeof(float) == 4, "");
    const int k1_smem = (16384 + 16384 + 128 + 64 + 132 + 256) * 4;
    const int k3_smem = (8192 + 64 * 68 + 1024 + 64 + 128 + 128 + 64) * 4;
    cudaFuncSetAttribute(k1_conv, cudaFuncAttributeMaxDynamicSharedMemorySize, k1_smem);
    cudaFuncSetAttribute(k3_out,  cudaFuncAttributeMaxDynamicSharedMemorySize, k3_smem);

    k0_prep<<<1, 128>>>(w3, b3, w5, b2, bg, bb, bm, bv);
    k1_conv<<<dim3(32, 8), 256, k1_smem>>>(x, w1, b1, w4, b4, w5);
    k2_sort<<<8, 1024>>>();
    k2_suffix_local<<<dim3(16, 8), 64>>>();
    k2_suffix_fix<<<dim3(16, 8), 64>>>();
    k3_out<<<dim3(64, 8), 256, k3_smem>>>(x, w2, out);
}

// round 2
// speedup vs baseline: 1.4506x; 1.4506x over previous
#include <cuda_runtime.h>

// B=8, C=128, IC=64, H=W=64, N=4096, M=1024 (pooled 32x32)

__device__ float g_wtp[132];
__device__ float g_bnA[128], g_bnB[128];
__device__ float g_t[8][4096];
__device__ float g_p[8][1024];
__device__ float g_xg[8][1024][64];
__device__ float g_psort[8][1024];
__device__ int   g_perm[8][1024];
__device__ float2 g_S12[8][1025][64];   // interleaved (S1,S2)

// ---------------------------------------------------------------------------
// K0: fold weights + BN constants
// ---------------------------------------------------------------------------
__global__ void k0_prep(const float* __restrict__ w3, const float* __restrict__ b3,
                        const float* __restrict__ w5, const float* __restrict__ b2,
                        const float* __restrict__ bg, const float* __restrict__ bb,
                        const float* __restrict__ bm, const float* __restrict__ bv) {
    int c = threadIdx.x;  // 0..127
    float acc = 0.f;
    #pragma unroll 16
    for (int i = 0; i < 64; i++) acc = fmaf(w5[i], w3[i * 128 + c], acc);
    g_wtp[c] = acc;
    if (c == 0) {
        float s = 0.f;
        for (int i = 0; i < 64; i++) s = fmaf(w5[i], b3[i], s);
        g_wtp[128] = s;
    }
    float inv = rsqrtf(bv[c] + 1e-5f);
    float al  = bg[c] * inv;
    g_bnA[c] = al;
    g_bnB[c] = (b2[c] - bm[c]) * al + bb[c];
}

// ---------------------------------------------------------------------------
// K1: fused conv1+conv4 GEMM (128x128 per pooled row), maxpool via shfl,
//     produces g_xg, g_p, and the folded scalar t per pixel.
// ---------------------------------------------------------------------------
__global__ void __launch_bounds__(256, 1)
k1_conv(const float* __restrict__ x,
        const float* __restrict__ w1, const float* __restrict__ b1,
        const float* __restrict__ w4, const float* __restrict__ b4,
        const float* __restrict__ w5) {
    extern __shared__ float sm[];
    float* sW    = sm;              // 128 oc x 128 c
    float* sX    = sm + 16384;      // 128 c  x 128 px
    float* sBias = sX + 16384;      // 128
    float* sWp   = sBias + 128;     // 64
    float* sWtp  = sWp + 64;        // 132
    float* sPred = sWtp + 132;      // 8 x 32

    const int tid = threadIdx.x;
    const int pr  = blockIdx.x;     // pooled row 0..31
    const int b   = blockIdx.y;

    const float4* w1v = (const float4*)w1;
    const float4* w4v = (const float4*)w4;
    #pragma unroll
    for (int k = 0; k < 16; k++) {
        int v  = tid + k * 256;
        int oc = v >> 5, c4 = v & 31;
        ((float4*)sW)[v] = (oc < 64) ? w1v[oc * 32 + c4] : w4v[(oc - 64) * 32 + c4];
    }
    const float4* xv = (const float4*)x;
    #pragma unroll
    for (int k = 0; k < 16; k++) {
        int v   = tid + k * 256;
        int rr  = v >> 4, c4 = v & 15;
        int c   = rr >> 1, r01 = rr & 1;
        ((float4*)sX)[c * 32 + r01 * 16 + c4] =
            xv[((b * 128 + c) * 64 + (2 * pr + r01)) * 16 + c4];
    }
    if (tid < 128) sBias[tid] = (tid < 64) ? b1[tid] : b4[tid - 64];
    if (tid < 64)  sWp[tid]   = w5[64 + tid];
    if (tid < 129) sWtp[tid]  = g_wtp[tid];
    __syncthreads();

    const int tx = tid & 15;
    const int ty = tid >> 4;

    float acc[8][8];
    #pragma unroll
    for (int u = 0; u < 8; u++)
        #pragma unroll
        for (int v = 0; v < 8; v++) acc[u][v] = 0.f;

    const float* xp  = sX + tx * 8;
    const float* wr  = sW + ty * 8 * 128;
    #pragma unroll 4
    for (int c = 0; c < 128; c++) {
        float4 xa = *(const float4*)(xp + c * 128);
        float4 xb = *(const float4*)(xp + c * 128 + 4);
        float xr[8] = {xa.x, xa.y, xa.z, xa.w, xb.x, xb.y, xb.z, xb.w};
        #pragma unroll
        for (int u = 0; u < 8; u++) {
            float wv = wr[u * 128 + c];
            #pragma unroll
            for (int v = 0; v < 8; v++) acc[u][v] = fmaf(wv, xr[v], acc[u][v]);
        }
    }

    if (tid < 128) {
        float a = sWtp[128];
        const float* xc = sX + tid;
        #pragma unroll 8
        for (int c = 0; c < 128; c++) a = fmaf(sWtp[c], xc[c * 128], a);
        int n = (2 * pr + (tid >> 6)) * 64 + (tid & 63);
        g_t[b][n] = a;
    }

    float pl[8][4];
    #pragma unroll
    for (int u = 0; u < 8; u++)
        #pragma unroll
        for (int q = 0; q < 4; q++) {
            float hm = fmaxf(acc[u][2 * q], acc[u][2 * q + 1]);
            float ot = __shfl_xor_sync(0xffffffffu, hm, 8);
            pl[u][q] = fmaxf(hm, ot);
        }

    if (tx < 8) {
        if (ty < 8) {
            float bbv[8];
            #pragma unroll
            for (int u = 0; u < 8; u++) bbv[u] = sBias[ty * 8 + u];
            int mb = pr * 32 + tx * 4;
            #pragma unroll
            for (int q = 0; q < 4; q++) {
                float4 lo = make_float4(pl[0][q] + bbv[0], pl[1][q] + bbv[1],
                                        pl[2][q] + bbv[2], pl[3][q] + bbv[3]);
                float4 hi = make_float4(pl[4][q] + bbv[4], pl[5][q] + bbv[5],
                                        pl[6][q] + bbv[6], pl[7][q] + bbv[7]);
                float* dst = &g_xg[b][mb + q][ty * 8];
                *(float4*)dst       = lo;
                *(float4*)(dst + 4) = hi;
            }
        } else {
            int g = ty - 8;
            #pragma unroll
            for (int q = 0; q < 4; q++) {
                float part = 0.f;
                #pragma unroll
                for (int u = 0; u < 8; u++)
                    part = fmaf(sWp[g * 8 + u], pl[u][q] + sBias[64 + g * 8 + u], part);
                sPred[g * 32 + tx * 4 + q] = part;
            }
        }
    }
    __syncthreads();
    if (tid < 32) {
        float pv = 0.f;
        #pragma unroll
        for (int g = 0; g < 8; g++) pv += sPred[g * 32 + tid];
        g_p[b][pr * 32 + tid] = pv;
    }
}

// ---------------------------------------------------------------------------
// K2a: bitonic sort on packed u64 keys (sortable-float<<32 | index).
// Warp shfl stages for dist<=16, smem only for dist>=32.
// ---------------------------------------------------------------------------
__global__ void __launch_bounds__(1024) k2_sort() {
    __shared__ unsigned long long sk[1024];
    const int b = blockIdx.x, tid = threadIdx.x;
    float v = g_p[b][tid];
    unsigned u = __float_as_uint(v);
    u = (u & 0x80000000u) ? ~u : (u | 0x80000000u);   // order-preserving map
    unsigned long long key = ((unsigned long long)u << 32) | (unsigned)tid;

    #pragma unroll
    for (int k = 2; k <= 1024; k <<= 1) {
        const bool up = ((tid & k) == 0);
        for (int j = k >> 1; j >= 32; j >>= 1) {
            sk[tid] = key;
            __syncthreads();
            unsigned long long ok = sk[tid ^ j];
            __syncthreads();
            bool takeMin = (((tid & j) == 0) == up);
            if ((key > ok) == takeMin) key = ok;
        }
        #pragma unroll
        for (int j = ((k >> 1) < 16 ? (k >> 1) : 16); j >= 1; j >>= 1) {
            unsigned long long ok = __shfl_xor_sync(0xffffffffu, key, j);
            bool takeMin = (((tid & j) == 0) == up);
            if ((key > ok) == takeMin) key = ok;
        }
    }
    int m = (int)(key & 1023u);
    g_perm[b][tid]  = m;
    g_psort[b][tid] = g_p[b][m];
}

// ---------------------------------------------------------------------------
// K2b: single-pass block-parallel suffix scan.
// grid (8 channel-groups of 8, 8 batch) x 1024 threads (one per sorted j).
// S12[b][j][i] = (sum_{j'>=j} v, sum_{j'>=j} p*v) with v = xg[perm[j']][i].
// ---------------------------------------------------------------------------
__global__ void __launch_bounds__(1024) k2_scan() {
    __shared__ float wt1[32], wt2[32], ws1[33], ws2[33];
    const int b = blockIdx.y, ig = blockIdx.x;
    const int tid = threadIdx.x, lane = tid & 31, w = tid >> 5;

    const int m  = g_perm[b][tid];
    const float pv = g_psort[b][tid];
    const float* row = g_xg[b][m];

    if (tid < 8) g_S12[b][1024][ig * 8 + tid] = make_float2(0.f, 0.f);

    #pragma unroll
    for (int c = 0; c < 8; c++) {
        const int i = ig * 8 + c;
        float v  = row[i];
        float s1 = v, s2 = pv * v;
        #pragma unroll
        for (int d = 1; d < 32; d <<= 1) {
            float t1 = __shfl_down_sync(0xffffffffu, s1, d);
            float t2 = __shfl_down_sync(0xffffffffu, s2, d);
            if (lane + d < 32) { s1 += t1; s2 += t2; }
        }
        if (lane == 0) { wt1[w] = s1; wt2[w] = s2; }
        __syncthreads();
        if (w == 0) {
            float a1 = wt1[lane], a2 = wt2[lane];
            #pragma unroll
            for (int d = 1; d < 32; d <<= 1) {
                float t1 = __shfl_down_sync(0xffffffffu, a1, d);
                float t2 = __shfl_down_sync(0xffffffffu, a2, d);
                if (lane + d < 32) { a1 += t1; a2 += t2; }
            }
            ws1[lane] = a1; ws2[lane] = a2;
            if (lane == 0) { ws1[32] = 0.f; ws2[32] = 0.f; }
        }
        __syncthreads();
        s1 += ws1[w + 1];
        s2 += ws2[w + 1];
        g_S12[b][tid][i] = make_float2(s1, s2);
        __syncthreads();   // protect wt/ws reuse next channel
    }
}

// ---------------------------------------------------------------------------
// K3: binary search k_n, build y tile, conv2 GEMM + BN + residual.
// ---------------------------------------------------------------------------
__global__ void __launch_bounds__(256)
k3_out(const float* __restrict__ x, const float* __restrict__ w2,
       float* __restrict__ out) {
    extern __shared__ float sm[];
    float* sW2 = sm;              // 128 co x 64 i
    float* sYT = sW2 + 8192;      // 64 i x 68 (padded) n
    float* sPs = sYT + 64 * 68;   // 1024
    float* sT  = sPs + 1024;      // 64
    float* sA  = sT + 64;         // 128
    float* sB  = sA + 128;        // 128
    int*   sK  = (int*)(sB + 128);// 64

    int tid = threadIdx.x;
    int tile = blockIdx.x, b = blockIdx.y;
    int n0 = tile * 64;

    const float4* w2v = (const float4*)w2;
    #pragma unroll
    for (int k = 0; k < 8; k++) ((float4*)sW2)[tid + k * 256] = w2v[tid + k * 256];
    #pragma unroll
    for (int k = 0; k < 4; k++) sPs[tid + k * 256] = g_psort[b][tid + k * 256];
    if (tid < 64)  sT[tid] = g_t[b][n0 + tid];
    if (tid < 128) { sA[tid] = g_bnA[tid]; sB[tid] = g_bnB[tid]; }
    __syncthreads();

    if (tid < 64) {
        float key = -sT[tid];
        int lo = 0, hi = 1024;
        while (lo < hi) { int mid = (lo + hi) >> 1; if (sPs[mid] > key) hi = mid; else lo = mid + 1; }
        sK[tid] = lo;
    }
    __syncthreads();

    {
        int iv = tid & 63, ng = tid >> 6;
        #pragma unroll 4
        for (int w = 0; w < 16; w++) {
            int n = ng * 16 + w;
            int k = sK[n];
            float t  = sT[n];
            float2 s = g_S12[b][k][iv];
            sYT[iv * 68 + n] = fmaf(t, s.x, s.y) * (1.0f / 1024.0f);
        }
    }
    __syncthreads();

    int tx = tid & 15, ty = tid >> 4;
    float acc[8][4];
    #pragma unroll
    for (int u = 0; u < 8; u++)
        #pragma unroll
        for (int v = 0; v < 4; v++) acc[u][v] = 0.f;

    #pragma unroll 4
    for (int i = 0; i < 64; i++) {
        float4 yv = *(const float4*)(sYT + i * 68 + tx * 4);
        #pragma unroll
        for (int u = 0; u < 8; u++) {
            float wv = sW2[(ty * 8 + u) * 64 + i];
            acc[u][0] = fmaf(wv, yv.x, acc[u][0]);
            acc[u][1] = fmaf(wv, yv.y, acc[u][1]);
            acc[u][2] = fmaf(wv, yv.z, acc[u][2]);
            acc[u][3] = fmaf(wv, yv.w, acc[u][3]);
        }
    }

    #pragma unroll
    for (int u = 0; u < 8; u++) {
        int oc = ty * 8 + u;
        long idx = ((long)(b * 128 + oc)) * 4096 + n0 + tx * 4;
        float4 xr = *(const float4*)(x + idx);
        float a = sA[oc], bv = sB[oc];
        float4 o;
        o.x = fmaf(acc[u][0], a, bv) + xr.x;
        o.y = fmaf(acc[u][1], a, bv) + xr.y;
        o.z = fmaf(acc[u][2], a, bv) + xr.z;
        o.w = fmaf(acc[u][3], a, bv) + xr.w;
        *((float4*)(out + idx)) = o;
    }
}

// ---------------------------------------------------------------------------
extern "C" void kernel_launch(void* const* d_in, const int* in_sizes, int n_in,
                              void* d_out, int out_size) {
    const float* x  = (const float*)d_in[0];
    const float* w1 = (const float*)d_in[1];
    const float* b1 = (const float*)d_in[2];
    const float* w3 = (const float*)d_in[3];
    const float* b3 = (const float*)d_in[4];
    const float* w4 = (const float*)d_in[5];
    const float* b4 = (const float*)d_in[6];
    const float* w5 = (const float*)d_in[7];
    const float* w2 = (const float*)d_in[8];
    const float* b2 = (const float*)d_in[9];
    const float* bg = (const float*)d_in[10];
    const float* bb = (const float*)d_in[11];
    const float* bm = (const float*)d_in[12];
    const float* bv = (const float*)d_in[13];
    float* out = (float*)d_out;

    const int k1_smem = (16384 + 16384 + 128 + 64 + 132 + 256) * 4;
    const int k3_smem = (8192 + 64 * 68 + 1024 + 64 + 128 + 128 + 64) * 4;
    cudaFuncSetAttribute(k1_conv, cudaFuncAttributeMaxDynamicSharedMemorySize, k1_smem);
    cudaFuncSetAttribute(k3_out,  cudaFuncAttributeMaxDynamicSharedMemorySize, k3_smem);

    k0_prep<<<1, 128>>>(w3, b3, w5, b2, bg, bb, bm, bv);
    k1_conv<<<dim3(32, 8), 256, k1_smem>>>(x, w1, b1, w4, b4, w5);
    k2_sort<<<8, 1024>>>();
    k2_scan<<<dim3(8, 8), 1024>>>();
    k3_out<<<dim3(64, 8), 256, k3_smem>>>(x, w2, out);
}

// round 3
// speedup vs baseline: 1.6948x; 1.1683x over previous
#include <cuda_runtime.h>

// B=8, C=128, IC=64, H=W=64, N=4096, M=1024 (pooled 32x32)

__device__ float g_wtp[132];
__device__ float g_bnA[128], g_bnB[128];
__device__ float g_t[8][4096];
__device__ float g_p[8][1024];
__device__ float g_xg[8][1024][64];
__device__ float g_psort[8][1024];
__device__ int   g_perm[8][1024];
__device__ float2 g_S12[8][1025][64];   // interleaved (S1,S2)

// ---- f32x2 packed helpers (sm_103a FFMA2) ---------------------------------
__device__ __forceinline__ void ffma2(unsigned long long& d,
                                      unsigned long long a, unsigned long long b) {
    asm("fma.rn.f32x2 %0, %1, %2, %0;" : "+l"(d) : "l"(a), "l"(b));
}
__device__ __forceinline__ unsigned long long pack2(float v) {
    unsigned long long r; asm("mov.b64 %0, {%1, %1};" : "=l"(r) : "f"(v)); return r;
}
__device__ __forceinline__ float2 unpack2(unsigned long long v) {
    float2 f; asm("mov.b64 {%0, %1}, %2;" : "=f"(f.x), "=f"(f.y) : "l"(v)); return f;
}

// ---------------------------------------------------------------------------
// K0: fold weights + BN constants
// ---------------------------------------------------------------------------
__global__ void k0_prep(const float* __restrict__ w3, const float* __restrict__ b3,
                        const float* __restrict__ w5, const float* __restrict__ b2,
                        const float* __restrict__ bg, const float* __restrict__ bb,
                        const float* __restrict__ bm, const float* __restrict__ bv) {
    int c = threadIdx.x;  // 0..127
    float acc = 0.f;
    #pragma unroll 16
    for (int i = 0; i < 64; i++) acc = fmaf(w5[i], w3[i * 128 + c], acc);
    g_wtp[c] = acc;
    if (c == 0) {
        float s = 0.f;
        for (int i = 0; i < 64; i++) s = fmaf(w5[i], b3[i], s);
        g_wtp[128] = s;
    }
    float inv = rsqrtf(bv[c] + 1e-5f);
    float al  = bg[c] * inv;
    g_bnA[c] = al;
    g_bnB[c] = (b2[c] - bm[c]) * al + bb[c];
}

// ---------------------------------------------------------------------------
// K1: fused conv1+conv4 GEMM (128x128 per pooled row) with f32x2 FMA,
//     maxpool via packed halves + shfl; produces g_xg, g_p, g_t.
// ---------------------------------------------------------------------------
__global__ void __launch_bounds__(256, 1)
k1_conv(const float* __restrict__ x,
        const float* __restrict__ w1, const float* __restrict__ b1,
        const float* __restrict__ w4, const float* __restrict__ b4,
        const float* __restrict__ w5) {
    extern __shared__ float sm[];
    float* sW    = sm;              // 128 oc x 128 c
    float* sX    = sm + 16384;      // 128 c  x 128 px
    float* sBias = sX + 16384;      // 128
    float* sWp   = sBias + 128;     // 64
    float* sWtp  = sWp + 64;        // 132
    float* sPred = sWtp + 132;      // 8 x 32

    const int tid = threadIdx.x;
    const int pr  = blockIdx.x;     // pooled row 0..31
    const int b   = blockIdx.y;

    const float4* w1v = (const float4*)w1;
    const float4* w4v = (const float4*)w4;
    #pragma unroll
    for (int k = 0; k < 16; k++) {
        int v  = tid + k * 256;
        int oc = v >> 5, c4 = v & 31;
        ((float4*)sW)[v] = (oc < 64) ? w1v[oc * 32 + c4] : w4v[(oc - 64) * 32 + c4];
    }
    const float4* xv = (const float4*)x;
    #pragma unroll
    for (int k = 0; k < 16; k++) {
        int v   = tid + k * 256;
        int rr  = v >> 4, c4 = v & 15;
        int c   = rr >> 1, r01 = rr & 1;
        ((float4*)sX)[c * 32 + r01 * 16 + c4] =
            xv[((b * 128 + c) * 64 + (2 * pr + r01)) * 16 + c4];
    }
    if (tid < 128) sBias[tid] = (tid < 64) ? b1[tid] : b4[tid - 64];
    if (tid < 64)  sWp[tid]   = w5[64 + tid];
    if (tid < 129) sWtp[tid]  = g_wtp[tid];
    __syncthreads();

    const int tx = tid & 15;
    const int ty = tid >> 4;

    // packed accumulators: acc2[u][q] holds pixels (tx*8+2q, tx*8+2q+1)
    unsigned long long acc2[8][4];
    #pragma unroll
    for (int u = 0; u < 8; u++)
        #pragma unroll
        for (int q = 0; q < 4; q++) acc2[u][q] = 0ull;

    const float* xp = sX + tx * 8;
    const float* wr = sW + ty * 8 * 128;
    #pragma unroll 4
    for (int c = 0; c < 128; c++) {
        ulonglong2 xa = *(const ulonglong2*)(xp + c * 128);       // pairs (0,1),(2,3)
        ulonglong2 xb = *(const ulonglong2*)(xp + c * 128 + 4);   // pairs (4,5),(6,7)
        #pragma unroll
        for (int u = 0; u < 8; u++) {
            unsigned long long wp = pack2(wr[u * 128 + c]);
            ffma2(acc2[u][0], wp, xa.x);
            ffma2(acc2[u][1], wp, xa.y);
            ffma2(acc2[u][2], wp, xb.x);
            ffma2(acc2[u][3], wp, xb.y);
        }
    }

    // t (folded conv3 dot): one pixel per thread for tid<128
    if (tid < 128) {
        float a = sWtp[128];
        const float* xc = sX + tid;
        #pragma unroll 8
        for (int c = 0; c < 128; c++) a = fmaf(sWtp[c], xc[c * 128], a);
        int n = (2 * pr + (tid >> 6)) * 64 + (tid & 63);
        g_t[b][n] = a;
    }

    // maxpool: horizontal = max of packed halves, vertical via shfl_xor(8)
    float pl[8][4];
    #pragma unroll
    for (int u = 0; u < 8; u++)
        #pragma unroll
        for (int q = 0; q < 4; q++) {
            float2 h = unpack2(acc2[u][q]);
            float hm = fmaxf(h.x, h.y);
            float ot = __shfl_xor_sync(0xffffffffu, hm, 8);
            pl[u][q] = fmaxf(hm, ot);
        }

    if (tx < 8) {
        if (ty < 8) {
            float bbv[8];
            #pragma unroll
            for (int u = 0; u < 8; u++) bbv[u] = sBias[ty * 8 + u];
            int mb = pr * 32 + tx * 4;
            #pragma unroll
            for (int q = 0; q < 4; q++) {
                float4 lo = make_float4(pl[0][q] + bbv[0], pl[1][q] + bbv[1],
                                        pl[2][q] + bbv[2], pl[3][q] + bbv[3]);
                float4 hi = make_float4(pl[4][q] + bbv[4], pl[5][q] + bbv[5],
                                        pl[6][q] + bbv[6], pl[7][q] + bbv[7]);
                float* dst = &g_xg[b][mb + q][ty * 8];
                *(float4*)dst       = lo;
                *(float4*)(dst + 4) = hi;
            }
        } else {
            int g = ty - 8;
            #pragma unroll
            for (int q = 0; q < 4; q++) {
                float part = 0.f;
                #pragma unroll
                for (int u = 0; u < 8; u++)
                    part = fmaf(sWp[g * 8 + u], pl[u][q] + sBias[64 + g * 8 + u], part);
                sPred[g * 32 + tx * 4 + q] = part;
            }
        }
    }
    __syncthreads();
    if (tid < 32) {
        float pv = 0.f;
        #pragma unroll
        for (int g = 0; g < 8; g++) pv += sPred[g * 32 + tid];
        g_p[b][pr * 32 + tid] = pv;
    }
}

// ---------------------------------------------------------------------------
// K2a: bitonic sort on packed u64 keys (sortable-float<<32 | index)
// ---------------------------------------------------------------------------
__global__ void __launch_bounds__(1024) k2_sort() {
    __shared__ unsigned long long sk[1024];
    const int b = blockIdx.x, tid = threadIdx.x;
    float v = g_p[b][tid];
    unsigned u = __float_as_uint(v);
    u = (u & 0x80000000u) ? ~u : (u | 0x80000000u);
    unsigned long long key = ((unsigned long long)u << 32) | (unsigned)tid;

    #pragma unroll
    for (int k = 2; k <= 1024; k <<= 1) {
        const bool up = ((tid & k) == 0);
        for (int j = k >> 1; j >= 32; j >>= 1) {
            sk[tid] = key;
            __syncthreads();
            unsigned long long ok = sk[tid ^ j];
            __syncthreads();
            bool takeMin = (((tid & j) == 0) == up);
            if ((key > ok) == takeMin) key = ok;
        }
        #pragma unroll
        for (int j = ((k >> 1) < 16 ? (k >> 1) : 16); j >= 1; j >>= 1) {
            unsigned long long ok = __shfl_xor_sync(0xffffffffu, key, j);
            bool takeMin = (((tid & j) == 0) == up);
            if ((key > ok) == takeMin) key = ok;
        }
    }
    int m = (int)(key & 1023u);
    g_perm[b][tid]  = m;
    g_psort[b][tid] = g_p[b][m];
}

// ---------------------------------------------------------------------------
// K2b: batched suffix scan — all 8 channels in registers, 2 syncthreads.
// grid (8 channel-groups, 8 batch) x 1024 threads (one per sorted j).
// ---------------------------------------------------------------------------
__global__ void __launch_bounds__(1024) k2_scan() {
    __shared__ float wt1[8][32], wt2[8][32], ws1[8][33], ws2[8][33];
    const int b = blockIdx.y, ig = blockIdx.x;
    const int tid = threadIdx.x, lane = tid & 31, w = tid >> 5;

    const int   m  = g_perm[b][tid];
    const float pv = g_psort[b][tid];
    const float* row = &g_xg[b][m][ig * 8];

    float4 va = *(const float4*)row;
    float4 vb = *(const float4*)(row + 4);
    float s1[8] = {va.x, va.y, va.z, va.w, vb.x, vb.y, vb.z, vb.w};
    float s2[8];
    #pragma unroll
    for (int c = 0; c < 8; c++) s2[c] = pv * s1[c];

    if (tid < 8) g_S12[b][1024][ig * 8 + tid] = make_float2(0.f, 0.f);

    // warp-level inclusive suffix scan, 16-wide ILP per stage
    #pragma unroll
    for (int d = 1; d < 32; d <<= 1) {
        bool take = (lane + d < 32);
        #pragma unroll
        for (int c = 0; c < 8; c++) {
            float t1 = __shfl_down_sync(0xffffffffu, s1[c], d);
            float t2 = __shfl_down_sync(0xffffffffu, s2[c], d);
            if (take) { s1[c] += t1; s2[c] += t2; }
        }
    }
    if (lane == 0) {
        #pragma unroll
        for (int c = 0; c < 8; c++) { wt1[c][w] = s1[c]; wt2[c][w] = s2[c]; }
    }
    __syncthreads();
    if (w < 8) {   // warp w combines channel w across the 32 warps
        float a1 = wt1[w][lane], a2 = wt2[w][lane];
        #pragma unroll
        for (int d = 1; d < 32; d <<= 1) {
            float t1 = __shfl_down_sync(0xffffffffu, a1, d);
            float t2 = __shfl_down_sync(0xffffffffu, a2, d);
            if (lane + d < 32) { a1 += t1; a2 += t2; }
        }
        ws1[w][lane] = a1; ws2[w][lane] = a2;
        if (lane == 0) { ws1[w][32] = 0.f; ws2[w][32] = 0.f; }
    }
    __syncthreads();

    // add cross-warp offsets and write 64 contiguous bytes per thread
    float2* dst = &g_S12[b][tid][ig * 8];
    #pragma unroll
    for (int c = 0; c < 8; c += 2) {
        float4 o;
        o.x = s1[c]     + ws1[c][w + 1];
        o.y = s2[c]     + ws2[c][w + 1];
        o.z = s1[c + 1] + ws1[c + 1][w + 1];
        o.w = s2[c + 1] + ws2[c + 1][w + 1];
        *(float4*)(dst + c) = o;
    }
}

// ---------------------------------------------------------------------------
// K3: binary search k_n, build y tile, conv2 GEMM (f32x2) + BN + residual.
// ---------------------------------------------------------------------------
__global__ void __launch_bounds__(256)
k3_out(const float* __restrict__ x, const float* __restrict__ w2,
       float* __restrict__ out) {
    extern __shared__ float sm[];
    float* sW2 = sm;              // 128 co x 64 i
    float* sYT = sW2 + 8192;      // 64 i x 68 (padded) n
    float* sPs = sYT + 64 * 68;   // 1024
    float* sT  = sPs + 1024;      // 64
    float* sA  = sT + 64;         // 128
    float* sB  = sA + 128;        // 128
    int*   sK  = (int*)(sB + 128);// 64

    int tid = threadIdx.x;
    int tile = blockIdx.x, b = blockIdx.y;
    int n0 = tile * 64;

    const float4* w2v = (const float4*)w2;
    #pragma unroll
    for (int k = 0; k < 8; k++) ((float4*)sW2)[tid + k * 256] = w2v[tid + k * 256];
    #pragma unroll
    for (int k = 0; k < 4; k++) sPs[tid + k * 256] = g_psort[b][tid + k * 256];
    if (tid < 64)  sT[tid] = g_t[b][n0 + tid];
    if (tid < 128) { sA[tid] = g_bnA[tid]; sB[tid] = g_bnB[tid]; }
    __syncthreads();

    if (tid < 64) {
        float key = -sT[tid];
        int lo = 0, hi = 1024;
        while (lo < hi) { int mid = (lo + hi) >> 1; if (sPs[mid] > key) hi = mid; else lo = mid + 1; }
        sK[tid] = lo;
    }
    __syncthreads();

    {
        int iv = tid & 63, ng = tid >> 6;
        #pragma unroll 4
        for (int w = 0; w < 16; w++) {
            int n = ng * 16 + w;
            int k = sK[n];
            float t  = sT[n];
            float2 s = g_S12[b][k][iv];
            sYT[iv * 68 + n] = fmaf(t, s.x, s.y) * (1.0f / 1024.0f);
        }
    }
    __syncthreads();

    int tx = tid & 15, ty = tid >> 4;
    unsigned long long acc2[8][2];   // pixel pairs (tx*4+0,1) (tx*4+2,3)
    #pragma unroll
    for (int u = 0; u < 8; u++) { acc2[u][0] = 0ull; acc2[u][1] = 0ull; }

    #pragma unroll 4
    for (int i = 0; i < 64; i++) {
        ulonglong2 yv = *(const ulonglong2*)(sYT + i * 68 + tx * 4);
        #pragma unroll
        for (int u = 0; u < 8; u++) {
            unsigned long long wp = pack2(sW2[(ty * 8 + u) * 64 + i]);
            ffma2(acc2[u][0], wp, yv.x);
            ffma2(acc2[u][1], wp, yv.y);
        }
    }

    #pragma unroll
    for (int u = 0; u < 8; u++) {
        int oc = ty * 8 + u;
        long idx = ((long)(b * 128 + oc)) * 4096 + n0 + tx * 4;
        float4 xr = *(const float4*)(x + idx);
        float a = sA[oc], bv = sB[oc];
        float2 p0 = unpack2(acc2[u][0]);
        float2 p1 = unpack2(acc2[u][1]);
        float4 o;
        o.x = fmaf(p0.x, a, bv) + xr.x;
        o.y = fmaf(p0.y, a, bv) + xr.y;
        o.z = fmaf(p1.x, a, bv) + xr.z;
        o.w = fmaf(p1.y, a, bv) + xr.w;
        *((float4*)(out + idx)) = o;
    }
}

// ---------------------------------------------------------------------------
extern "C" void kernel_launch(void* const* d_in, const int* in_sizes, int n_in,
                              void* d_out, int out_size) {
    const float* x  = (const float*)d_in[0];
    const float* w1 = (const float*)d_in[1];
    const float* b1 = (const float*)d_in[2];
    const float* w3 = (const float*)d_in[3];
    const float* b3 = (const float*)d_in[4];
    const float* w4 = (const float*)d_in[5];
    const float* b4 = (const float*)d_in[6];
    const float* w5 = (const float*)d_in[7];
    const float* w2 = (const float*)d_in[8];
    const float* b2 = (const float*)d_in[9];
    const float* bg = (const float*)d_in[10];
    const float* bb = (const float*)d_in[11];
    const float* bm = (const float*)d_in[12];
    const float* bv = (const float*)d_in[13];
    float* out = (float*)d_out;

    const int k1_smem = (16384 + 16384 + 128 + 64 + 132 + 256) * 4;
    const int k3_smem = (8192 + 64 * 68 + 1024 + 64 + 128 + 128 + 64) * 4;
    cudaFuncSetAttribute(k1_conv, cudaFuncAttributeMaxDynamicSharedMemorySize, k1_smem);
    cudaFuncSetAttribute(k3_out,  cudaFuncAttributeMaxDynamicSharedMemorySize, k3_smem);

    k0_prep<<<1, 128>>>(w3, b3, w5, b2, bg, bb, bm, bv);
    k1_conv<<<dim3(32, 8), 256, k1_smem>>>(x, w1, b1, w4, b4, w5);
    k2_sort<<<8, 1024>>>();
    k2_scan<<<dim3(8, 8), 1024>>>();
    k3_out<<<dim3(64, 8), 256, k3_smem>>>(x, w2, out);
}

// round 4
// speedup vs baseline: 2.5221x; 1.4881x over previous
#include <cuda_runtime.h>
#include <cuda_bf16.h>

// B=8, C=128, IC=64, H=W=64, N=4096, M=1024 (pooled 32x32)

__device__ float g_wtp[132];
__device__ float g_bnA[128], g_bnB[128];
__device__ float g_t[8][4096];
__device__ float g_p[8][1024];
__device__ float g_xg[8][1024][64];
__device__ float g_psort[8][1024];
__device__ int   g_perm[8][1024];
__device__ float2 g_S12[8][1025][64];   // interleaved (S1,S2)

// ---- helpers --------------------------------------------------------------
__device__ __forceinline__ void ffma2(unsigned long long& d,
                                      unsigned long long a, unsigned long long b) {
    asm("fma.rn.f32x2 %0, %1, %2, %0;" : "+l"(d) : "l"(a), "l"(b));
}
__device__ __forceinline__ unsigned long long pack2(float v) {
    unsigned long long r; asm("mov.b64 %0, {%1, %1};" : "=l"(r) : "f"(v)); return r;
}
__device__ __forceinline__ float2 unpack2(unsigned long long v) {
    float2 f; asm("mov.b64 {%0, %1}, %2;" : "=f"(f.x), "=f"(f.y) : "l"(v)); return f;
}
// pack (lo,hi) floats -> bf16x2 word (lo in low half)
__device__ __forceinline__ unsigned pbf2(float lo, float hi) {
    unsigned r; asm("cvt.rn.bf16x2.f32 %0, %1, %2;" : "=r"(r) : "f"(hi), "f"(lo));
    return r;
}
__device__ __forceinline__ void mma16816(float* d, unsigned a0, unsigned a1,
                                         unsigned a2, unsigned a3,
                                         unsigned b0, unsigned b1) {
    asm("mma.sync.aligned.m16n8k16.row.col.f32.bf16.bf16.f32 "
        "{%0,%1,%2,%3}, {%4,%5,%6,%7}, {%8,%9}, {%0,%1,%2,%3};"
        : "+f"(d[0]), "+f"(d[1]), "+f"(d[2]), "+f"(d[3])
        : "r"(a0), "r"(a1), "r"(a2), "r"(a3), "r"(b0), "r"(b1));
}

// ---------------------------------------------------------------------------
// K0: fold weights + BN constants
// ---------------------------------------------------------------------------
__global__ void k0_prep(const float* __restrict__ w3, const float* __restrict__ b3,
                        const float* __restrict__ w5, const float* __restrict__ b2,
                        const float* __restrict__ bg, const float* __restrict__ bb,
                        const float* __restrict__ bm, const float* __restrict__ bv) {
    int c = threadIdx.x;  // 0..127
    float acc = 0.f;
    #pragma unroll 16
    for (int i = 0; i < 64; i++) acc = fmaf(w5[i], w3[i * 128 + c], acc);
    g_wtp[c] = acc;
    if (c == 0) {
        float s = 0.f;
        for (int i = 0; i < 64; i++) s = fmaf(w5[i], b3[i], s);
        g_wtp[128] = s;
    }
    float inv = rsqrtf(bv[c] + 1e-5f);
    float al  = bg[c] * inv;
    g_bnA[c] = al;
    g_bnB[c] = (b2[c] - bm[c]) * al + bb[c];
}

// ---------------------------------------------------------------------------
// K1: fused conv1+conv4 via bf16 mma.sync (m16n8k16), in-register maxpool.
// Layouts (k-pair packed bf16x2):
//   sWb[oc][cc]  : (w[oc][2cc], w[oc][2cc+1]), row stride 68 words
//   sXb[cc][px]  : (x[2cc][px], x[2cc+1][px]), row stride 136 words
// grid (32 pooled-rows, 8 batch), 256 threads (8 warps; warp w: oc [16w,16w+16))
// ---------------------------------------------------------------------------
#define SWS 68
#define SXS 136
__global__ void __launch_bounds__(256, 2)
k1_conv(const float* __restrict__ x,
        const float* __restrict__ w1, const float* __restrict__ b1,
        const float* __restrict__ w4, const float* __restrict__ b4,
        const float* __restrict__ w5) {
    extern __shared__ unsigned smu[];
    unsigned* sWb  = smu;                    // 128*68
    unsigned* sXb  = smu + 128 * SWS;        // 64*136
    float* sBias = (float*)(sXb + 64 * SXS); // 128
    float* sWp   = sBias + 128;              // 64
    float* sWtp  = sWp + 64;                 // 129
    float* sPred = sWtp + 129;               // 4*32

    const int tid = threadIdx.x;
    const int pr  = blockIdx.x;              // pooled row 0..31
    const int b   = blockIdx.y;

    // ---- load + pack weights: [oc][c] f32 -> bf16x2 pairs
    const float4* w1v = (const float4*)w1;
    const float4* w4v = (const float4*)w4;
    #pragma unroll
    for (int k = 0; k < 16; k++) {
        int v  = tid + k * 256;              // 0..4095 float4s
        int oc = v >> 5, c4 = v & 31;
        float4 f = (oc < 64) ? w1v[oc * 32 + c4] : w4v[(oc - 64) * 32 + c4];
        unsigned q0 = pbf2(f.x, f.y);
        unsigned q1 = pbf2(f.z, f.w);
        *(uint2*)&sWb[oc * SWS + c4 * 2] = make_uint2(q0, q1);
    }
    // ---- load + pack x: channel pairs (2cc,2cc+1) for 2 image rows
    const float4* xv = (const float4*)x;
    #pragma unroll
    for (int it = 0; it < 8; it++) {
        int v   = tid + it * 256;            // 0..2047 units
        int cc  = v >> 5, u = v & 31;
        int r01 = u >> 4, c4 = u & 15;
        long base = ((long)(b * 128) << 10);  // *1024 float4s per channel? (64*16)
        float4 fa = xv[((b * 128 + 2 * cc) * 64 + (2 * pr + r01)) * 16 + c4];
        float4 fb = xv[((b * 128 + 2 * cc + 1) * 64 + (2 * pr + r01)) * 16 + c4];
        (void)base;
        uint4 q;
        q.x = pbf2(fa.x, fb.x); q.y = pbf2(fa.y, fb.y);
        q.z = pbf2(fa.z, fb.z); q.w = pbf2(fa.w, fb.w);
        *(uint4*)&sXb[cc * SXS + r01 * 64 + c4 * 4] = q;
    }
    if (tid < 128) sBias[tid] = (tid < 64) ? b1[tid] : b4[tid - 64];
    if (tid < 64)  sWp[tid]   = w5[64 + tid];
    if (tid < 129) sWtp[tid]  = g_wtp[tid];
    __syncthreads();

    const int w    = tid >> 5;
    const int lane = tid & 31;
    const int g    = lane >> 2;
    const int m4   = lane & 3;
    const int ocb  = w * 16;

    float acc[16][4];
    #pragma unroll
    for (int t = 0; t < 16; t++)
        #pragma unroll
        for (int r = 0; r < 4; r++) acc[t][r] = 0.f;

    #pragma unroll
    for (int s = 0; s < 8; s++) {            // k16 steps
        const int cc0 = s * 8;
        unsigned a0 = sWb[(ocb + g)     * SWS + cc0 + m4];
        unsigned a1 = sWb[(ocb + g + 8) * SWS + cc0 + m4];
        unsigned a2 = sWb[(ocb + g)     * SWS + cc0 + 4 + m4];
        unsigned a3 = sWb[(ocb + g + 8) * SWS + cc0 + 4 + m4];
        #pragma unroll
        for (int t = 0; t < 16; t++) {
            unsigned b0 = sXb[(cc0 + m4)     * SXS + t * 8 + g];
            unsigned b1 = sXb[(cc0 + 4 + m4) * SXS + t * 8 + g];
            mma16816(acc[t], a0, a1, a2, a3, b0, b1);
        }
    }

    // ---- t (folded conv3 dot), one pixel per thread for tid<128
    if (tid < 128) {
        float a = sWtp[128];
        #pragma unroll 8
        for (int cc = 0; cc < 64; cc++) {
            unsigned u = sXb[cc * SXS + tid];
            __nv_bfloat162 h = *reinterpret_cast<__nv_bfloat162*>(&u);
            float2 f = __bfloat1622float2(h);
            a = fmaf(sWtp[2 * cc], f.x, a);
            a = fmaf(sWtp[2 * cc + 1], f.y, a);
        }
        int n = (2 * pr + (tid >> 6)) * 64 + (tid & 63);
        g_t[b][n] = a;
    }

    // ---- maxpool in registers: cols (2m4,2m4+1) horiz pair; tiles t/t+8 vert
    float pg[8], pg8[8];
    #pragma unroll
    for (int t = 0; t < 8; t++) {
        pg[t]  = fmaxf(fmaxf(acc[t][0], acc[t][1]), fmaxf(acc[t + 8][0], acc[t + 8][1]));
        pg8[t] = fmaxf(fmaxf(acc[t][2], acc[t][3]), fmaxf(acc[t + 8][2], acc[t + 8][3]));
    }

    if (w < 4) {  // xg path: oc 0..63
        int oc0 = ocb + g, oc1 = ocb + g + 8;
        float b0v = sBias[oc0], b1v = sBias[oc1];
        #pragma unroll
        for (int t = 0; t < 8; t++) {
            int mb = pr * 32 + t * 4 + m4;
            g_xg[b][mb][oc0] = pg[t]  + b0v;
            g_xg[b][mb][oc1] = pg8[t] + b1v;
        }
    } else {      // p path: oc 64..127, dot with wp
        int oc0 = ocb + g, oc1 = ocb + g + 8;
        float wp0 = sWp[oc0 - 64], wp1 = sWp[oc1 - 64];
        float b0v = sBias[oc0], b1v = sBias[oc1];
        float part[8];
        #pragma unroll
        for (int t = 0; t < 8; t++)
            part[t] = fmaf(wp0, pg[t] + b0v, wp1 * (pg8[t] + b1v));
        #pragma unroll
        for (int d = 4; d < 32; d <<= 1) {
            #pragma unroll
            for (int t = 0; t < 8; t++)
                part[t] += __shfl_xor_sync(0xffffffffu, part[t], d);
        }
        if (lane < 4) {
            #pragma unroll
            for (int t = 0; t < 8; t++)
                sPred[(w - 4) * 32 + t * 4 + lane] = part[t];
        }
    }
    __syncthreads();
    if (tid < 32) {
        float pv = sPred[tid] + sPred[32 + tid] + sPred[64 + tid] + sPred[96 + tid];
        g_p[b][pr * 32 + tid] = pv;
    }
}

// ---------------------------------------------------------------------------
// K2a: bitonic sort on packed u64 keys, ping-pong smem (1 sync per stage)
// ---------------------------------------------------------------------------
__global__ void __launch_bounds__(1024) k2_sort() {
    __shared__ unsigned long long skA[1024], skB[1024];
    const int b = blockIdx.x, tid = threadIdx.x;
    float v = g_p[b][tid];
    unsigned u = __float_as_uint(v);
    u = (u & 0x80000000u) ? ~u : (u | 0x80000000u);
    unsigned long long key = ((unsigned long long)u << 32) | (unsigned)tid;

    int pb = 0;
    #pragma unroll
    for (int k = 2; k <= 1024; k <<= 1) {
        const bool up = ((tid & k) == 0);
        for (int j = k >> 1; j >= 32; j >>= 1) {
            unsigned long long* buf = pb ? skB : skA;
            buf[tid] = key;
            __syncthreads();
            unsigned long long ok = buf[tid ^ j];
            pb ^= 1;
            bool takeMin = (((tid & j) == 0) == up);
            if ((key > ok) == takeMin) key = ok;
        }
        #pragma unroll
        for (int j = ((k >> 1) < 16 ? (k >> 1) : 16); j >= 1; j >>= 1) {
            unsigned long long ok = __shfl_xor_sync(0xffffffffu, key, j);
            bool takeMin = (((tid & j) == 0) == up);
            if ((key > ok) == takeMin) key = ok;
        }
    }
    int m = (int)(key & 1023u);
    g_perm[b][tid]  = m;
    g_psort[b][tid] = g_p[b][m];
}

// ---------------------------------------------------------------------------
// K2b: batched suffix scan, 4 channels per block -> grid (16,8)=128 blocks
// ---------------------------------------------------------------------------
__global__ void __launch_bounds__(1024) k2_scan() {
    __shared__ float wt1[4][32], wt2[4][32], ws1[4][33], ws2[4][33];
    const int b = blockIdx.y, ig = blockIdx.x;        // ig 0..15
    const int tid = threadIdx.x, lane = tid & 31, w = tid >> 5;

    const int   m  = g_perm[b][tid];
    const float pv = g_psort[b][tid];

    float4 va = *(const float4*)&g_xg[b][m][ig * 4];
    float s1[4] = {va.x, va.y, va.z, va.w};
    float s2[4];
    #pragma unroll
    for (int c = 0; c < 4; c++) s2[c] = pv * s1[c];

    if (tid < 4) g_S12[b][1024][ig * 4 + tid] = make_float2(0.f, 0.f);

    #pragma unroll
    for (int d = 1; d < 32; d <<= 1) {
        bool take = (lane + d < 32);
        #pragma unroll
        for (int c = 0; c < 4; c++) {
            float t1 = __shfl_down_sync(0xffffffffu, s1[c], d);
            float t2 = __shfl_down_sync(0xffffffffu, s2[c], d);
            if (take) { s1[c] += t1; s2[c] += t2; }
        }
    }
    if (lane == 0) {
        #pragma unroll
        for (int c = 0; c < 4; c++) { wt1[c][w] = s1[c]; wt2[c][w] = s2[c]; }
    }
    __syncthreads();
    if (w < 4) {
        float a1 = wt1[w][lane], a2 = wt2[w][lane];
        #pragma unroll
        for (int d = 1; d < 32; d <<= 1) {
            float t1 = __shfl_down_sync(0xffffffffu, a1, d);
            float t2 = __shfl_down_sync(0xffffffffu, a2, d);
            if (lane + d < 32) { a1 += t1; a2 += t2; }
        }
        ws1[w][lane] = a1; ws2[w][lane] = a2;
        if (lane == 0) { ws1[w][32] = 0.f; ws2[w][32] = 0.f; }
    }
    __syncthreads();

    float2* dst = &g_S12[b][tid][ig * 4];
    float4 o0, o1;
    o0.x = s1[0] + ws1[0][w + 1];  o0.y = s2[0] + ws2[0][w + 1];
    o0.z = s1[1] + ws1[1][w + 1];  o0.w = s2[1] + ws2[1][w + 1];
    o1.x = s1[2] + ws1[2][w + 1];  o1.y = s2[2] + ws2[2][w + 1];
    o1.z = s1[3] + ws1[3][w + 1];  o1.w = s2[3] + ws2[3][w + 1];
    *(float4*)(dst)     = o0;
    *(float4*)(dst + 2) = o1;
}

// ---------------------------------------------------------------------------
// K3: binary search k_n, build y tile, conv2 GEMM (f32x2) + BN + residual.
// ---------------------------------------------------------------------------
__global__ void __launch_bounds__(256)
k3_out(const float* __restrict__ x, const float* __restrict__ w2,
       float* __restrict__ out) {
    extern __shared__ float sm[];
    float* sW2 = sm;              // 128 co x 64 i
    float* sYT = sW2 + 8192;      // 64 i x 68 (padded) n
    float* sPs = sYT + 64 * 68;   // 1024
    float* sT  = sPs + 1024;      // 64
    float* sA  = sT + 64;         // 128
    float* sB  = sA + 128;        // 128
    int*   sK  = (int*)(sB + 128);// 64

    int tid = threadIdx.x;
    int tile = blockIdx.x, b = blockIdx.y;
    int n0 = tile * 64;

    const float4* w2v = (const float4*)w2;
    #pragma unroll
    for (int k = 0; k < 8; k++) ((float4*)sW2)[tid + k * 256] = w2v[tid + k * 256];
    #pragma unroll
    for (int k = 0; k < 4; k++) sPs[tid + k * 256] = g_psort[b][tid + k * 256];
    if (tid < 64)  sT[tid] = g_t[b][n0 + tid];
    if (tid < 128) { sA[tid] = g_bnA[tid]; sB[tid] = g_bnB[tid]; }
    __syncthreads();

    if (tid < 64) {
        float key = -sT[tid];
        int lo = 0, hi = 1024;
        while (lo < hi) { int mid = (lo + hi) >> 1; if (sPs[mid] > key) hi = mid; else lo = mid + 1; }
        sK[tid] = lo;
    }
    __syncthreads();

    {
        int iv = tid & 63, ng = tid >> 6;
        #pragma unroll 4
        for (int w = 0; w < 16; w++) {
            int n = ng * 16 + w;
            int k = sK[n];
            float t  = sT[n];
            float2 s = g_S12[b][k][iv];
            sYT[iv * 68 + n] = fmaf(t, s.x, s.y) * (1.0f / 1024.0f);
        }
    }
    __syncthreads();

    int tx = tid & 15, ty = tid >> 4;
    unsigned long long acc2[8][2];
    #pragma unroll
    for (int u = 0; u < 8; u++) { acc2[u][0] = 0ull; acc2[u][1] = 0ull; }

    #pragma unroll 4
    for (int i = 0; i < 64; i++) {
        ulonglong2 yv = *(const ulonglong2*)(sYT + i * 68 + tx * 4);
        #pragma unroll
        for (int u = 0; u < 8; u++) {
            unsigned long long wp = pack2(sW2[(ty * 8 + u) * 64 + i]);
            ffma2(acc2[u][0], wp, yv.x);
            ffma2(acc2[u][1], wp, yv.y);
        }
    }

    #pragma unroll
    for (int u = 0; u < 8; u++) {
        int oc = ty * 8 + u;
        long idx = ((long)(b * 128 + oc)) * 4096 + n0 + tx * 4;
        float4 xr = *(const float4*)(x + idx);
        float a = sA[oc], bv = sB[oc];
        float2 p0 = unpack2(acc2[u][0]);
        float2 p1 = unpack2(acc2[u][1]);
        float4 o;
        o.x = fmaf(p0.x, a, bv) + xr.x;
        o.y = fmaf(p0.y, a, bv) + xr.y;
        o.z = fmaf(p1.x, a, bv) + xr.z;
        o.w = fmaf(p1.y, a, bv) + xr.w;
        *((float4*)(out + idx)) = o;
    }
}

// ---------------------------------------------------------------------------
extern "C" void kernel_launch(void* const* d_in, const int* in_sizes, int n_in,
                              void* d_out, int out_size) {
    const float* x  = (const float*)d_in[0];
    const float* w1 = (const float*)d_in[1];
    const float* b1 = (const float*)d_in[2];
    const float* w3 = (const float*)d_in[3];
    const float* b3 = (const float*)d_in[4];
    const float* w4 = (const float*)d_in[5];
    const float* b4 = (const float*)d_in[6];
    const float* w5 = (const float*)d_in[7];
    const float* w2 = (const float*)d_in[8];
    const float* b2 = (const float*)d_in[9];
    const float* bg = (const float*)d_in[10];
    const float* bb = (const float*)d_in[11];
    const float* bm = (const float*)d_in[12];
    const float* bv = (const float*)d_in[13];
    float* out = (float*)d_out;

    const int k1_smem = (128 * SWS + 64 * SXS) * 4 + (128 + 64 + 129 + 128) * 4;
    const int k3_smem = (8192 + 64 * 68 + 1024 + 64 + 128 + 128 + 64) * 4;
    cudaFuncSetAttribute(k1_conv, cudaFuncAttributeMaxDynamicSharedMemorySize, k1_smem);
    cudaFuncSetAttribute(k3_out,  cudaFuncAttributeMaxDynamicSharedMemorySize, k3_smem);

    k0_prep<<<1, 128>>>(w3, b3, w5, b2, bg, bb, bm, bv);
    k1_conv<<<dim3(32, 8), 256, k1_smem>>>(x, w1, b1, w4, b4, w5);
    k2_sort<<<8, 1024>>>();
    k2_scan<<<dim3(16, 8), 1024>>>();
    k3_out<<<dim3(64, 8), 256, k3_smem>>>(x, w2, out);
}

// round 5
// speedup vs baseline: 2.7336x; 1.0839x over previous
#include <cuda_runtime.h>
#include <cuda_bf16.h>

// B=8, C=128, IC=64, H=W=64, N=4096, M=1024 (pooled 32x32)

__device__ float g_wtp[132];
__device__ float g_bnA[128], g_bnB[128];
__device__ float g_p[8][1024];
__device__ float g_xg[8][1024][64];
__device__ float g_psort[8][1024];
__device__ int   g_perm[8][1024];
__device__ float2 g_S12[8][1025][64];     // interleaved (S1,S2)
__device__ unsigned g_w2b[128 * 32];      // w2 packed bf16x2 pairs [co][ii]

// ---- helpers --------------------------------------------------------------
// pack (lo,hi) floats -> bf16x2 word (lo in low half)
__device__ __forceinline__ unsigned pbf2(float lo, float hi) {
    unsigned r; asm("cvt.rn.bf16x2.f32 %0, %1, %2;" : "=r"(r) : "f"(hi), "f"(lo));
    return r;
}
__device__ __forceinline__ void mma16816(float* d, unsigned a0, unsigned a1,
                                         unsigned a2, unsigned a3,
                                         unsigned b0, unsigned b1) {
    asm("mma.sync.aligned.m16n8k16.row.col.f32.bf16.bf16.f32 "
        "{%0,%1,%2,%3}, {%4,%5,%6,%7}, {%8,%9}, {%0,%1,%2,%3};"
        : "+f"(d[0]), "+f"(d[1]), "+f"(d[2]), "+f"(d[3])
        : "r"(a0), "r"(a1), "r"(a2), "r"(a3), "r"(b0), "r"(b1));
}

// ---------------------------------------------------------------------------
// K0: fold weights + BN constants + pack w2 to bf16
// ---------------------------------------------------------------------------
__global__ void k0_prep(const float* __restrict__ w3, const float* __restrict__ b3,
                        const float* __restrict__ w5, const float* __restrict__ b2,
                        const float* __restrict__ bg, const float* __restrict__ bb,
                        const float* __restrict__ bm, const float* __restrict__ bv,
                        const float* __restrict__ w2) {
    int c = threadIdx.x;  // 0..127
    float acc = 0.f;
    #pragma unroll 16
    for (int i = 0; i < 64; i++) acc = fmaf(w5[i], w3[i * 128 + c], acc);
    g_wtp[c] = acc;
    if (c == 0) {
        float s = 0.f;
        for (int i = 0; i < 64; i++) s = fmaf(w5[i], b3[i], s);
        g_wtp[128] = s;
    }
    float inv = rsqrtf(bv[c] + 1e-5f);
    float al  = bg[c] * inv;
    g_bnA[c] = al;
    g_bnB[c] = (b2[c] - bm[c]) * al + bb[c];

    // pack w2 [co=c][i 0..63] -> 32 bf16x2 words
    const float4* w2v = (const float4*)w2;
    #pragma unroll
    for (int q4 = 0; q4 < 8; q4++) {
        float4 f0 = w2v[c * 16 + q4 * 2];
        float4 f1 = w2v[c * 16 + q4 * 2 + 1];
        uint4 o;
        o.x = pbf2(f0.x, f0.y); o.y = pbf2(f0.z, f0.w);
        o.z = pbf2(f1.x, f1.y); o.w = pbf2(f1.z, f1.w);
        *(uint4*)&g_w2b[c * 32 + q4 * 4] = o;
    }
}

// ---------------------------------------------------------------------------
// K1: fused conv1+conv4 via bf16 mma.sync, in-register maxpool.
//   sWb[oc][cc] : (w[oc][2cc], w[oc][2cc+1]), stride 68
//   sXb[cc][px] : (x[2cc][px], x[2cc+1][px]), stride 136
// grid (32 pooled-rows, 8 batch), 256 threads
// ---------------------------------------------------------------------------
#define SWS 68
#define SXS 136
__global__ void __launch_bounds__(256, 2)
k1_conv(const float* __restrict__ x,
        const float* __restrict__ w1, const float* __restrict__ b1,
        const float* __restrict__ w4, const float* __restrict__ b4,
        const float* __restrict__ w5) {
    extern __shared__ unsigned smu[];
    unsigned* sWb  = smu;                    // 128*68
    unsigned* sXb  = smu + 128 * SWS;        // 64*136
    float* sBias = (float*)(sXb + 64 * SXS); // 128
    float* sWp   = sBias + 128;              // 64
    float* sPred = sWp + 64;                 // 4*32

    const int tid = threadIdx.x;
    const int pr  = blockIdx.x;
    const int b   = blockIdx.y;

    const float4* w1v = (const float4*)w1;
    const float4* w4v = (const float4*)w4;
    #pragma unroll
    for (int k = 0; k < 16; k++) {
        int v  = tid + k * 256;
        int oc = v >> 5, c4 = v & 31;
        float4 f = (oc < 64) ? w1v[oc * 32 + c4] : w4v[(oc - 64) * 32 + c4];
        *(uint2*)&sWb[oc * SWS + c4 * 2] = make_uint2(pbf2(f.x, f.y), pbf2(f.z, f.w));
    }
    const float4* xv = (const float4*)x;
    #pragma unroll
    for (int it = 0; it < 8; it++) {
        int v   = tid + it * 256;
        int cc  = v >> 5, u = v & 31;
        int r01 = u >> 4, c4 = u & 15;
        float4 fa = xv[((b * 128 + 2 * cc) * 64 + (2 * pr + r01)) * 16 + c4];
        float4 fb = xv[((b * 128 + 2 * cc + 1) * 64 + (2 * pr + r01)) * 16 + c4];
        uint4 q;
        q.x = pbf2(fa.x, fb.x); q.y = pbf2(fa.y, fb.y);
        q.z = pbf2(fa.z, fb.z); q.w = pbf2(fa.w, fb.w);
        *(uint4*)&sXb[cc * SXS + r01 * 64 + c4 * 4] = q;
    }
    if (tid < 128) sBias[tid] = (tid < 64) ? b1[tid] : b4[tid - 64];
    if (tid < 64)  sWp[tid]   = w5[64 + tid];
    __syncthreads();

    const int w    = tid >> 5;
    const int lane = tid & 31;
    const int g    = lane >> 2;
    const int m4   = lane & 3;
    const int ocb  = w * 16;

    float acc[16][4];
    #pragma unroll
    for (int t = 0; t < 16; t++)
        #pragma unroll
        for (int r = 0; r < 4; r++) acc[t][r] = 0.f;

    #pragma unroll
    for (int s = 0; s < 8; s++) {
        const int cc0 = s * 8;
        unsigned a0 = sWb[(ocb + g)     * SWS + cc0 + m4];
        unsigned a1 = sWb[(ocb + g + 8) * SWS + cc0 + m4];
        unsigned a2 = sWb[(ocb + g)     * SWS + cc0 + 4 + m4];
        unsigned a3 = sWb[(ocb + g + 8) * SWS + cc0 + 4 + m4];
        #pragma unroll
        for (int t = 0; t < 16; t++) {
            unsigned b0 = sXb[(cc0 + m4)     * SXS + t * 8 + g];
            unsigned b1 = sXb[(cc0 + 4 + m4) * SXS + t * 8 + g];
            mma16816(acc[t], a0, a1, a2, a3, b0, b1);
        }
    }

    float pg[8], pg8[8];
    #pragma unroll
    for (int t = 0; t < 8; t++) {
        pg[t]  = fmaxf(fmaxf(acc[t][0], acc[t][1]), fmaxf(acc[t + 8][0], acc[t + 8][1]));
        pg8[t] = fmaxf(fmaxf(acc[t][2], acc[t][3]), fmaxf(acc[t + 8][2], acc[t + 8][3]));
    }

    if (w < 4) {  // xg path: oc 0..63
        int oc0 = ocb + g, oc1 = ocb + g + 8;
        float b0v = sBias[oc0], b1v = sBias[oc1];
        #pragma unroll
        for (int t = 0; t < 8; t++) {
            int mb = pr * 32 + t * 4 + m4;
            g_xg[b][mb][oc0] = pg[t]  + b0v;
            g_xg[b][mb][oc1] = pg8[t] + b1v;
        }
    } else {      // p path: oc 64..127 dotted with wp
        int oc0 = ocb + g, oc1 = ocb + g + 8;
        float wp0 = sWp[oc0 - 64], wp1 = sWp[oc1 - 64];
        float b0v = sBias[oc0], b1v = sBias[oc1];
        float part[8];
        #pragma unroll
        for (int t = 0; t < 8; t++)
            part[t] = fmaf(wp0, pg[t] + b0v, wp1 * (pg8[t] + b1v));
        #pragma unroll
        for (int d = 4; d < 32; d <<= 1) {
            #pragma unroll
            for (int t = 0; t < 8; t++)
                part[t] += __shfl_xor_sync(0xffffffffu, part[t], d);
        }
        if (lane < 4) {
            #pragma unroll
            for (int t = 0; t < 8; t++)
                sPred[(w - 4) * 32 + t * 4 + lane] = part[t];
        }
    }
    __syncthreads();
    if (tid < 32) {
        float pv = sPred[tid] + sPred[32 + tid] + sPred[64 + tid] + sPred[96 + tid];
        g_p[b][pr * 32 + tid] = pv;
    }
}

// ---------------------------------------------------------------------------
// K2a: bitonic sort on packed u64 keys, ping-pong smem
// ---------------------------------------------------------------------------
__global__ void __launch_bounds__(1024) k2_sort() {
    __shared__ unsigned long long skA[1024], skB[1024];
    const int b = blockIdx.x, tid = threadIdx.x;
    float v = g_p[b][tid];
    unsigned u = __float_as_uint(v);
    u = (u & 0x80000000u) ? ~u : (u | 0x80000000u);
    unsigned long long key = ((unsigned long long)u << 32) | (unsigned)tid;

    int pb = 0;
    #pragma unroll
    for (int k = 2; k <= 1024; k <<= 1) {
        const bool up = ((tid & k) == 0);
        for (int j = k >> 1; j >= 32; j >>= 1) {
            unsigned long long* buf = pb ? skB : skA;
            buf[tid] = key;
            __syncthreads();
            unsigned long long ok = buf[tid ^ j];
            pb ^= 1;
            bool takeMin = (((tid & j) == 0) == up);
            if ((key > ok) == takeMin) key = ok;
        }
        #pragma unroll
        for (int j = ((k >> 1) < 16 ? (k >> 1) : 16); j >= 1; j >>= 1) {
            unsigned long long ok = __shfl_xor_sync(0xffffffffu, key, j);
            bool takeMin = (((tid & j) == 0) == up);
            if ((key > ok) == takeMin) key = ok;
        }
    }
    int m = (int)(key & 1023u);
    g_perm[b][tid]  = m;
    g_psort[b][tid] = g_p[b][m];
}

// ---------------------------------------------------------------------------
// K2b: suffix scan, 512 threads x 2 sorted-positions x 2 channels.
// grid (32 channel-pairs, 8 batch) = 256 blocks.
// ---------------------------------------------------------------------------
__global__ void __launch_bounds__(512) k2_scan() {
    __shared__ float wt1[2][16], wt2[2][16], ws1[2][17], ws2[2][17];
    const int b = blockIdx.y, ig = blockIdx.x;            // channels ig*2, ig*2+1
    const int tid = threadIdx.x, lane = tid & 31, w = tid >> 5;   // w 0..15
    const int j0 = 2 * tid, j1 = j0 + 1;

    const int   m0 = g_perm[b][j0], m1 = g_perm[b][j1];
    const float p0 = g_psort[b][j0], p1 = g_psort[b][j1];
    float2 va = *(const float2*)&g_xg[b][m0][ig * 2];
    float2 vb = *(const float2*)&g_xg[b][m1][ig * 2];

    if (tid == 0) *(float4*)&g_S12[b][1024][ig * 2] = make_float4(0.f, 0.f, 0.f, 0.f);

    // per-channel pair sums
    float s1[2] = {va.x + vb.x, va.y + vb.y};
    float s2[2] = {fmaf(p0, va.x, p1 * vb.x), fmaf(p0, va.y, p1 * vb.y)};

    // warp inclusive suffix scan of pair sums
    #pragma unroll
    for (int d = 1; d < 32; d <<= 1) {
        bool take = (lane + d < 32);
        #pragma unroll
        for (int c = 0; c < 2; c++) {
            float t1 = __shfl_down_sync(0xffffffffu, s1[c], d);
            float t2 = __shfl_down_sync(0xffffffffu, s2[c], d);
            if (take) { s1[c] += t1; s2[c] += t2; }
        }
    }
    if (lane == 0) {
        #pragma unroll
        for (int c = 0; c < 2; c++) { wt1[c][w] = s1[c]; wt2[c][w] = s2[c]; }
    }
    __syncthreads();
    if (tid < 32) {
        int l = (lane < 16) ? lane : 15;
        float a1[2], a2[2];
        #pragma unroll
        for (int c = 0; c < 2; c++) { a1[c] = wt1[c][l]; a2[c] = wt2[c][l]; }
        #pragma unroll
        for (int d = 1; d < 16; d <<= 1) {
            bool take = (lane + d < 16);
            #pragma unroll
            for (int c = 0; c < 2; c++) {
                float t1 = __shfl_down_sync(0xffffffffu, a1[c], d);
                float t2 = __shfl_down_sync(0xffffffffu, a2[c], d);
                if (take) { a1[c] += t1; a2[c] += t2; }
            }
        }
        if (lane < 16) {
            #pragma unroll
            for (int c = 0; c < 2; c++) { ws1[c][lane] = a1[c]; ws2[c][lane] = a2[c]; }
        }
        if (lane == 0) {
            #pragma unroll
            for (int c = 0; c < 2; c++) { ws1[c][16] = 0.f; ws2[c][16] = 0.f; }
        }
    }
    __syncthreads();

    // S at j0 (includes own pair); S at j1 = S(j0) - v(j0)
    float S1j0[2], S2j0[2];
    #pragma unroll
    for (int c = 0; c < 2; c++) {
        S1j0[c] = s1[c] + ws1[c][w + 1];
        S2j0[c] = s2[c] + ws2[c][w + 1];
    }
    float4 o0, o1;
    o0.x = S1j0[0]; o0.y = S2j0[0]; o0.z = S1j0[1]; o0.w = S2j0[1];
    o1.x = S1j0[0] - va.x;           o1.y = S2j0[0] - p0 * va.x;
    o1.z = S1j0[1] - va.y;           o1.w = S2j0[1] - p0 * va.y;
    *(float4*)&g_S12[b][j0][ig * 2] = o0;
    *(float4*)&g_S12[b][j1][ig * 2] = o1;
}

// ---------------------------------------------------------------------------
// K3: x tile -> smem; t = wtp.x (fp32); binary search; y packed bf16;
//     conv2 via bf16 mma.sync; BN + residual epilogue.
// grid (64 tiles, 8 batch), 256 threads
// ---------------------------------------------------------------------------
#define W2S 36
#define YBS 68
__global__ void __launch_bounds__(256)
k3_out(const float* __restrict__ x, float* __restrict__ out) {
    extern __shared__ float sm[];
    float*    sX   = sm;                         // 128 c x 64 n
    unsigned* sW2b = (unsigned*)(sm + 8192);     // 128*36
    unsigned* sYb  = sW2b + 128 * W2S;           // 32*68
    float*    sPs  = (float*)(sYb + 32 * YBS);   // 1024
    float*    sWtp = sPs + 1024;                 // 132
    float*    sT   = sWtp + 132;                 // 64
    float*    sA   = sT + 64;                    // 128
    float*    sB   = sA + 128;                   // 128
    float*    sPart= sB + 128;                   // 4 x 64
    int*      sK   = (int*)(sPart + 256);        // 64

    const int tid = threadIdx.x;
    const int tile = blockIdx.x, b = blockIdx.y;
    const int n0 = tile * 64;

    // x tile: 2048 float4
    const float4* xv = (const float4*)x;
    #pragma unroll
    for (int k = 0; k < 8; k++) {
        int v = tid + k * 256;
        int c = v >> 4, n4 = v & 15;
        ((float4*)sX)[c * 16 + n4] = xv[((b * 128 + c) << 10) + tile * 16 + n4];
    }
    // packed w2: 1024 uint4, re-strided to 36
    const uint4* w2b4 = (const uint4*)g_w2b;
    #pragma unroll
    for (int k = 0; k < 4; k++) {
        int v = tid + k * 256;
        int co = v >> 3, q4 = v & 7;
        *(uint4*)&sW2b[co * W2S + q4 * 4] = w2b4[co * 8 + q4];
    }
    ((float4*)sPs)[tid] = ((const float4*)g_psort[b])[tid];
    if (tid < 132) sWtp[tid] = g_wtp[tid < 129 ? tid : 128];
    if (tid < 128) { sA[tid] = g_bnA[tid]; sB[tid] = g_bnB[tid]; }
    __syncthreads();

    // t partials: quarter q sums channels q*32..q*32+31
    {
        int n = tid & 63, q = tid >> 6;
        float a = 0.f;
        const float* xc = sX + q * 32 * 64 + n;
        const float* wc = sWtp + q * 32;
        #pragma unroll 8
        for (int c = 0; c < 32; c++) a = fmaf(wc[c], xc[c * 64], a);
        sPart[q * 64 + n] = a;
    }
    __syncthreads();
    if (tid < 64) {
        float t = sWtp[128] + sPart[tid] + sPart[64 + tid] + sPart[128 + tid] + sPart[192 + tid];
        sT[tid] = t;
        float key = -t;
        int lo = 0, hi = 1024;
        while (lo < hi) { int mid = (lo + hi) >> 1; if (sPs[mid] > key) hi = mid; else lo = mid + 1; }
        sK[tid] = lo;
    }
    __syncthreads();

    // build y packed bf16: word ii at col n
    {
        int n = tid >> 2, q = tid & 3;
        int k = sK[n];
        float t = sT[n];
        const float4* s4 = (const float4*)&g_S12[b][k][q * 16];
        #pragma unroll
        for (int r = 0; r < 8; r++) {
            float4 s = s4[r];
            float y0 = fmaf(t, s.x, s.y) * (1.0f / 1024.0f);
            float y1 = fmaf(t, s.z, s.w) * (1.0f / 1024.0f);
            sYb[(q * 8 + r) * YBS + n] = pbf2(y0, y1);
        }
    }
    __syncthreads();

    const int w    = tid >> 5;
    const int lane = tid & 31;
    const int g    = lane >> 2;
    const int m4   = lane & 3;
    const int ocb  = w * 16;

    float acc[8][4];
    #pragma unroll
    for (int t = 0; t < 8; t++)
        #pragma unroll
        for (int r = 0; r < 4; r++) acc[t][r] = 0.f;

    #pragma unroll
    for (int s = 0; s < 4; s++) {
        const int ii0 = s * 8;
        unsigned a0 = sW2b[(ocb + g)     * W2S + ii0 + m4];
        unsigned a1 = sW2b[(ocb + g + 8) * W2S + ii0 + m4];
        unsigned a2 = sW2b[(ocb + g)     * W2S + ii0 + 4 + m4];
        unsigned a3 = sW2b[(ocb + g + 8) * W2S + ii0 + 4 + m4];
        #pragma unroll
        for (int t = 0; t < 8; t++) {
            unsigned b0 = sYb[(ii0 + m4)     * YBS + t * 8 + g];
            unsigned b1 = sYb[(ii0 + 4 + m4) * YBS + t * 8 + g];
            mma16816(acc[t], a0, a1, a2, a3, b0, b1);
        }
    }

    // epilogue: BN + residual, float2 stores
    const int co0 = ocb + g, co1 = ocb + g + 8;
    const float A0 = sA[co0], B0 = sB[co0];
    const float A1 = sA[co1], B1 = sB[co1];
    #pragma unroll
    for (int t = 0; t < 8; t++) {
        int n = t * 8 + 2 * m4;
        float2 x0 = *(const float2*)&sX[co0 * 64 + n];
        float2 x1 = *(const float2*)&sX[co1 * 64 + n];
        float2 o0, o1;
        o0.x = fmaf(acc[t][0], A0, B0) + x0.x;
        o0.y = fmaf(acc[t][1], A0, B0) + x0.y;
        o1.x = fmaf(acc[t][2], A1, B1) + x1.x;
        o1.y = fmaf(acc[t][3], A1, B1) + x1.y;
        *(float2*)&out[((long)(b * 128 + co0) << 12) + n0 + n] = o0;
        *(float2*)&out[((long)(b * 128 + co1) << 12) + n0 + n] = o1;
    }
}

// ---------------------------------------------------------------------------
extern "C" void kernel_launch(void* const* d_in, const int* in_sizes, int n_in,
                              void* d_out, int out_size) {
    const float* x  = (const float*)d_in[0];
    const float* w1 = (const float*)d_in[1];
    const float* b1 = (const float*)d_in[2];
    const float* w3 = (const float*)d_in[3];
    const float* b3 = (const float*)d_in[4];
    const float* w4 = (const float*)d_in[5];
    const float* b4 = (const float*)d_in[6];
    const float* w5 = (const float*)d_in[7];
    const float* w2 = (const float*)d_in[8];
    const float* b2 = (const float*)d_in[9];
    const float* bg = (const float*)d_in[10];
    const float* bb = (const float*)d_in[11];
    const float* bm = (const float*)d_in[12];
    const float* bv = (const float*)d_in[13];
    float* out = (float*)d_out;

    const int k1_smem = (128 * SWS + 64 * SXS) * 4 + (128 + 64 + 128) * 4;
    const int k3_smem = (8192 + 128 * W2S + 32 * YBS + 1024 + 132 + 64 + 128 + 128 + 256 + 64) * 4;
    cudaFuncSetAttribute(k1_conv, cudaFuncAttributeMaxDynamicSharedMemorySize, k1_smem);
    cudaFuncSetAttribute(k3_out,  cudaFuncAttributeMaxDynamicSharedMemorySize, k3_smem);

    k0_prep<<<1, 128>>>(w3, b3, w5, b2, bg, bb, bm, bv, w2);
    k1_conv<<<dim3(32, 8), 256, k1_smem>>>(x, w1, b1, w4, b4, w5);
    k2_sort<<<8, 1024>>>();
    k2_scan<<<dim3(32, 8), 512>>>();
    k3_out<<<dim3(64, 8), 256, k3_smem>>>(x, out);
}

// round 6
// speedup vs baseline: 3.0154x; 1.1031x over previous
#include <cuda_runtime.h>
#include <cuda_bf16.h>

// B=8, C=128, IC=64, H=W=64, N=4096, M=1024 (pooled 32x32)

__device__ float g_p[8][1024];
__device__ float g_xg[8][1024][64];
__device__ float g_psort[8][1024];
__device__ int   g_perm[8][1024];
__device__ float2 g_S12[8][1025][64];     // interleaved (S1,S2)

// ---- helpers --------------------------------------------------------------
__device__ __forceinline__ unsigned pbf2(float lo, float hi) {
    unsigned r; asm("cvt.rn.bf16x2.f32 %0, %1, %2;" : "=r"(r) : "f"(hi), "f"(lo));
    return r;
}
__device__ __forceinline__ void mma16816(float* d, unsigned a0, unsigned a1,
                                         unsigned a2, unsigned a3,
                                         unsigned b0, unsigned b1) {
    asm("mma.sync.aligned.m16n8k16.row.col.f32.bf16.bf16.f32 "
        "{%0,%1,%2,%3}, {%4,%5,%6,%7}, {%8,%9}, {%0,%1,%2,%3};"
        : "+f"(d[0]), "+f"(d[1]), "+f"(d[2]), "+f"(d[3])
        : "r"(a0), "r"(a1), "r"(a2), "r"(a3), "r"(b0), "r"(b1));
}

// ---------------------------------------------------------------------------
// K1: fused conv1+conv4 via bf16 mma.sync, in-register maxpool.
// ---------------------------------------------------------------------------
#define SWS 68
#define SXS 136
__global__ void __launch_bounds__(256, 2)
k1_conv(const float* __restrict__ x,
        const float* __restrict__ w1, const float* __restrict__ b1,
        const float* __restrict__ w4, const float* __restrict__ b4,
        const float* __restrict__ w5) {
    extern __shared__ unsigned smu[];
    unsigned* sWb  = smu;                    // 128*68
    unsigned* sXb  = smu + 128 * SWS;        // 64*136
    float* sBias = (float*)(sXb + 64 * SXS); // 128
    float* sWp   = sBias + 128;              // 64
    float* sPred = sWp + 64;                 // 4*32

    const int tid = threadIdx.x;
    const int pr  = blockIdx.x;
    const int b   = blockIdx.y;

    const float4* w1v = (const float4*)w1;
    const float4* w4v = (const float4*)w4;
    #pragma unroll
    for (int k = 0; k < 16; k++) {
        int v  = tid + k * 256;
        int oc = v >> 5, c4 = v & 31;
        float4 f = (oc < 64) ? w1v[oc * 32 + c4] : w4v[(oc - 64) * 32 + c4];
        *(uint2*)&sWb[oc * SWS + c4 * 2] = make_uint2(pbf2(f.x, f.y), pbf2(f.z, f.w));
    }
    const float4* xv = (const float4*)x;
    #pragma unroll
    for (int it = 0; it < 8; it++) {
        int v   = tid + it * 256;
        int cc  = v >> 5, u = v & 31;
        int r01 = u >> 4, c4 = u & 15;
        float4 fa = xv[((b * 128 + 2 * cc) * 64 + (2 * pr + r01)) * 16 + c4];
        float4 fb = xv[((b * 128 + 2 * cc + 1) * 64 + (2 * pr + r01)) * 16 + c4];
        uint4 q;
        q.x = pbf2(fa.x, fb.x); q.y = pbf2(fa.y, fb.y);
        q.z = pbf2(fa.z, fb.z); q.w = pbf2(fa.w, fb.w);
        *(uint4*)&sXb[cc * SXS + r01 * 64 + c4 * 4] = q;
    }
    if (tid < 128) sBias[tid] = (tid < 64) ? b1[tid] : b4[tid - 64];
    if (tid < 64)  sWp[tid]   = w5[64 + tid];
    __syncthreads();

    const int w    = tid >> 5;
    const int lane = tid & 31;
    const int g    = lane >> 2;
    const int m4   = lane & 3;
    const int ocb  = w * 16;

    float acc[16][4];
    #pragma unroll
    for (int t = 0; t < 16; t++)
        #pragma unroll
        for (int r = 0; r < 4; r++) acc[t][r] = 0.f;

    #pragma unroll
    for (int s = 0; s < 8; s++) {
        const int cc0 = s * 8;
        unsigned a0 = sWb[(ocb + g)     * SWS + cc0 + m4];
        unsigned a1 = sWb[(ocb + g + 8) * SWS + cc0 + m4];
        unsigned a2 = sWb[(ocb + g)     * SWS + cc0 + 4 + m4];
        unsigned a3 = sWb[(ocb + g + 8) * SWS + cc0 + 4 + m4];
        #pragma unroll
        for (int t = 0; t < 16; t++) {
            unsigned b0 = sXb[(cc0 + m4)     * SXS + t * 8 + g];
            unsigned b1 = sXb[(cc0 + 4 + m4) * SXS + t * 8 + g];
            mma16816(acc[t], a0, a1, a2, a3, b0, b1);
        }
    }

    float pg[8], pg8[8];
    #pragma unroll
    for (int t = 0; t < 8; t++) {
        pg[t]  = fmaxf(fmaxf(acc[t][0], acc[t][1]), fmaxf(acc[t + 8][0], acc[t + 8][1]));
        pg8[t] = fmaxf(fmaxf(acc[t][2], acc[t][3]), fmaxf(acc[t + 8][2], acc[t + 8][3]));
    }

    if (w < 4) {  // xg path: oc 0..63
        int oc0 = ocb + g, oc1 = ocb + g + 8;
        float b0v = sBias[oc0], b1v = sBias[oc1];
        #pragma unroll
        for (int t = 0; t < 8; t++) {
            int mb = pr * 32 + t * 4 + m4;
            g_xg[b][mb][oc0] = pg[t]  + b0v;
            g_xg[b][mb][oc1] = pg8[t] + b1v;
        }
    } else {      // p path
        int oc0 = ocb + g, oc1 = ocb + g + 8;
        float wp0 = sWp[oc0 - 64], wp1 = sWp[oc1 - 64];
        float b0v = sBias[oc0], b1v = sBias[oc1];
        float part[8];
        #pragma unroll
        for (int t = 0; t < 8; t++)
            part[t] = fmaf(wp0, pg[t] + b0v, wp1 * (pg8[t] + b1v));
        #pragma unroll
        for (int d = 4; d < 32; d <<= 1) {
            #pragma unroll
            for (int t = 0; t < 8; t++)
                part[t] += __shfl_xor_sync(0xffffffffu, part[t], d);
        }
        if (lane < 4) {
            #pragma unroll
            for (int t = 0; t < 8; t++)
                sPred[(w - 4) * 32 + t * 4 + lane] = part[t];
        }
    }
    __syncthreads();
    if (tid < 32) {
        float pv = sPred[tid] + sPred[32 + tid] + sPred[64 + tid] + sPred[96 + tid];
        g_p[b][pr * 32 + tid] = pv;
    }
}

// ---------------------------------------------------------------------------
// K2a: bitonic sort on packed u64 keys, ping-pong smem
// ---------------------------------------------------------------------------
__global__ void __launch_bounds__(1024) k2_sort() {
    __shared__ unsigned long long skA[1024], skB[1024];
    const int b = blockIdx.x, tid = threadIdx.x;
    float v = g_p[b][tid];
    unsigned u = __float_as_uint(v);
    u = (u & 0x80000000u) ? ~u : (u | 0x80000000u);
    unsigned long long key = ((unsigned long long)u << 32) | (unsigned)tid;

    int pb = 0;
    #pragma unroll
    for (int k = 2; k <= 1024; k <<= 1) {
        const bool up = ((tid & k) == 0);
        for (int j = k >> 1; j >= 32; j >>= 1) {
            unsigned long long* buf = pb ? skB : skA;
            buf[tid] = key;
            __syncthreads();
            unsigned long long ok = buf[tid ^ j];
            pb ^= 1;
            bool takeMin = (((tid & j) == 0) == up);
            if ((key > ok) == takeMin) key = ok;
        }
        #pragma unroll
        for (int j = ((k >> 1) < 16 ? (k >> 1) : 16); j >= 1; j >>= 1) {
            unsigned long long ok = __shfl_xor_sync(0xffffffffu, key, j);
            bool takeMin = (((tid & j) == 0) == up);
            if ((key > ok) == takeMin) key = ok;
        }
    }
    int m = (int)(key & 1023u);
    g_perm[b][tid]  = m;
    g_psort[b][tid] = g_p[b][m];
}

// ---------------------------------------------------------------------------
// K2b: suffix scan, 256 threads x 4 consecutive j x 4 channels.
// grid (16 channel-quads, 8 batch) = 128 blocks. MLP=4 float4 gathers/thread.
// ---------------------------------------------------------------------------
__global__ void __launch_bounds__(256) k2_scan() {
    __shared__ float sm1[4][8], sm2[4][8];
    const int b = blockIdx.y, ig = blockIdx.x;          // channels ig*4..ig*4+3
    const int tid = threadIdx.x, lane = tid & 31, w = tid >> 5;  // 8 warps
    const int j0 = 4 * tid;

    if (tid == 0) {
        float2* z = &g_S12[b][1024][ig * 4];
        *(float4*)z       = make_float4(0.f, 0.f, 0.f, 0.f);
        *(float4*)(z + 2) = make_float4(0.f, 0.f, 0.f, 0.f);
    }

    const int4   pm = ((const int4*)g_perm[b])[tid];
    const float4 ps = ((const float4*)g_psort[b])[tid];

    // 4 independent gathers (MLP=4)
    float4 v0 = *(const float4*)&g_xg[b][pm.x][ig * 4];
    float4 v1 = *(const float4*)&g_xg[b][pm.y][ig * 4];
    float4 v2 = *(const float4*)&g_xg[b][pm.z][ig * 4];
    float4 v3 = *(const float4*)&g_xg[b][pm.w][ig * 4];
    float vv[4][4] = {{v0.x, v0.y, v0.z, v0.w}, {v1.x, v1.y, v1.z, v1.w},
                      {v2.x, v2.y, v2.z, v2.w}, {v3.x, v3.y, v3.z, v3.w}};
    float pp[4] = {ps.x, ps.y, ps.z, ps.w};

    // per-thread strip totals
    float s1[4], s2[4];
    #pragma unroll
    for (int c = 0; c < 4; c++) {
        s1[c] = vv[0][c] + vv[1][c] + vv[2][c] + vv[3][c];
        s2[c] = fmaf(pp[0], vv[0][c], fmaf(pp[1], vv[1][c],
                fmaf(pp[2], vv[2][c], pp[3] * vv[3][c])));
    }

    // warp inclusive suffix scan over lanes (8-wide ILP)
    #pragma unroll
    for (int d = 1; d < 32; d <<= 1) {
        bool take = (lane + d < 32);
        #pragma unroll
        for (int c = 0; c < 4; c++) {
            float t1 = __shfl_down_sync(0xffffffffu, s1[c], d);
            float t2 = __shfl_down_sync(0xffffffffu, s2[c], d);
            if (take) { s1[c] += t1; s2[c] += t2; }
        }
    }
    if (lane == 0) {
        #pragma unroll
        for (int c = 0; c < 4; c++) { sm1[c][w] = s1[c]; sm2[c][w] = s2[c]; }
    }
    __syncthreads();
    // each thread sums its own cross-warp carry (warps w' > w)
    #pragma unroll
    for (int c = 0; c < 4; c++) {
        float c1 = 0.f, c2 = 0.f;
        #pragma unroll
        for (int w2 = 0; w2 < 8; w2++)
            if (w2 > w) { c1 += sm1[c][w2]; c2 += sm2[c][w2]; }
        s1[c] += c1; s2[c] += c2;
    }

    // emit rows j0..j0+3 (S inclusive at j): peel own strip front-to-back
    float2* base = &g_S12[b][j0][ig * 4];
    #pragma unroll
    for (int k = 0; k < 4; k++) {
        float4 oa = make_float4(s1[0], s2[0], s1[1], s2[1]);
        float4 ob = make_float4(s1[2], s2[2], s1[3], s2[3]);
        float2* dst = base + (long)k * 64;
        *(float4*)dst       = oa;
        *(float4*)(dst + 2) = ob;
        if (k < 3) {
            #pragma unroll
            for (int c = 0; c < 4; c++) {
                s1[c] -= vv[k][c];
                s2[c] = fmaf(-pp[k], vv[k][c], s2[c]);
            }
        }
    }
}

// ---------------------------------------------------------------------------
// K3: folds (wtp, BN, w2 pack) per block; x tile -> smem; t = wtp.x (fp32);
//     binary search; y packed bf16; conv2 via bf16 mma.sync; BN + residual.
// grid (64 tiles, 8 batch), 256 threads
// ---------------------------------------------------------------------------
#define W2S 36
#define YBS 68
__global__ void __launch_bounds__(256)
k3_out(const float* __restrict__ x,
       const float* __restrict__ w3, const float* __restrict__ b3,
       const float* __restrict__ w5, const float* __restrict__ w2,
       const float* __restrict__ b2,
       const float* __restrict__ bg, const float* __restrict__ bb,
       const float* __restrict__ bm, const float* __restrict__ bv,
       float* __restrict__ out) {
    extern __shared__ float sm[];
    float*    sX   = sm;                         // 128 c x 64 n
    unsigned* sW2b = (unsigned*)(sm + 8192);     // 128*36
    unsigned* sYb  = sW2b + 128 * W2S;           // 32*68
    float*    sPs  = (float*)(sYb + 32 * YBS);   // 1024
    float*    sWtp = sPs + 1024;                 // 132
    float*    sT   = sWtp + 132;                 // 64
    float*    sA   = sT + 64;                    // 128
    float*    sB   = sA + 128;                   // 128
    float*    sPart= sB + 128;                   // 4 x 64
    int*      sK   = (int*)(sPart + 256);        // 64

    const int tid = threadIdx.x;
    const int tile = blockIdx.x, b = blockIdx.y;
    const int n0 = tile * 64;

    // x tile: 2048 float4
    const float4* xv = (const float4*)x;
    #pragma unroll
    for (int k = 0; k < 8; k++) {
        int v = tid + k * 256;
        int c = v >> 4, n4 = v & 15;
        ((float4*)sX)[c * 16 + n4] = xv[((b * 128 + c) << 10) + tile * 16 + n4];
    }
    // pack w2 (f32 -> bf16x2), re-strided to 36
    const float4* w2v = (const float4*)w2;
    #pragma unroll
    for (int k = 0; k < 8; k++) {
        int v = tid + k * 256;
        int co = v >> 4, q4 = v & 15;
        float4 f = w2v[v];
        *(uint2*)&sW2b[co * W2S + q4 * 2] = make_uint2(pbf2(f.x, f.y), pbf2(f.z, f.w));
    }
    ((float4*)sPs)[tid] = ((const float4*)g_psort[b])[tid];
    // fold wtp + BN constants
    if (tid < 128) {
        float acc = 0.f;
        #pragma unroll 16
        for (int i = 0; i < 64; i++) acc = fmaf(w5[i], w3[i * 128 + tid], acc);
        sWtp[tid] = acc;
        float inv = rsqrtf(bv[tid] + 1e-5f);
        float al  = bg[tid] * inv;
        sA[tid] = al;
        sB[tid] = (b2[tid] - bm[tid]) * al + bb[tid];
    } else if (tid < 160) {
        int l = tid - 128;
        float s = fmaf(w5[l], b3[l], w5[l + 32] * b3[l + 32]);
        #pragma unroll
        for (int d = 16; d >= 1; d >>= 1)
            s += __shfl_xor_sync(0xffffffffu, s, d);
        if (l == 0) sWtp[128] = s;
    }
    __syncthreads();

    // t partials: quarter q sums channels q*32..q*32+31
    {
        int n = tid & 63, q = tid >> 6;
        float a = 0.f;
        const float* xc = sX + q * 32 * 64 + n;
        const float* wc = sWtp + q * 32;
        #pragma unroll 8
        for (int c = 0; c < 32; c++) a = fmaf(wc[c], xc[c * 64], a);
        sPart[q * 64 + n] = a;
    }
    __syncthreads();
    if (tid < 64) {
        float t = sWtp[128] + sPart[tid] + sPart[64 + tid] + sPart[128 + tid] + sPart[192 + tid];
        sT[tid] = t;
        float key = -t;
        int lo = 0, hi = 1024;
        while (lo < hi) { int mid = (lo + hi) >> 1; if (sPs[mid] > key) hi = mid; else lo = mid + 1; }
        sK[tid] = lo;
    }
    __syncthreads();

    // build y packed bf16: word ii at col n
    {
        int n = tid >> 2, q = tid & 3;
        int k = sK[n];
        float t = sT[n];
        const float4* s4 = (const float4*)&g_S12[b][k][q * 16];
        #pragma unroll
        for (int r = 0; r < 8; r++) {
            float4 s = s4[r];
            float y0 = fmaf(t, s.x, s.y) * (1.0f / 1024.0f);
            float y1 = fmaf(t, s.z, s.w) * (1.0f / 1024.0f);
            sYb[(q * 8 + r) * YBS + n] = pbf2(y0, y1);
        }
    }
    __syncthreads();

    const int w    = tid >> 5;
    const int lane = tid & 31;
    const int g    = lane >> 2;
    const int m4   = lane & 3;
    const int ocb  = w * 16;

    float acc[8][4];
    #pragma unroll
    for (int t = 0; t < 8; t++)
        #pragma unroll
        for (int r = 0; r < 4; r++) acc[t][r] = 0.f;

    #pragma unroll
    for (int s = 0; s < 4; s++) {
        const int ii0 = s * 8;
        unsigned a0 = sW2b[(ocb + g)     * W2S + ii0 + m4];
        unsigned a1 = sW2b[(ocb + g + 8) * W2S + ii0 + m4];
        unsigned a2 = sW2b[(ocb + g)     * W2S + ii0 + 4 + m4];
        unsigned a3 = sW2b[(ocb + g + 8) * W2S + ii0 + 4 + m4];
        #pragma unroll
        for (int t = 0; t < 8; t++) {
            unsigned b0 = sYb[(ii0 + m4)     * YBS + t * 8 + g];
            unsigned b1 = sYb[(ii0 + 4 + m4) * YBS + t * 8 + g];
            mma16816(acc[t], a0, a1, a2, a3, b0, b1);
        }
    }

    // epilogue: BN + residual
    const int co0 = ocb + g, co1 = ocb + g + 8;
    const float A0 = sA[co0], B0 = sB[co0];
    const float A1 = sA[co1], B1 = sB[co1];
    #pragma unroll
    for (int t = 0; t < 8; t++) {
        int n = t * 8 + 2 * m4;
        float2 x0 = *(const float2*)&sX[co0 * 64 + n];
        float2 x1 = *(const float2*)&sX[co1 * 64 + n];
        float2 o0, o1;
        o0.x = fmaf(acc[t][0], A0, B0) + x0.x;
        o0.y = fmaf(acc[t][1], A0, B0) + x0.y;
        o1.x = fmaf(acc[t][2], A1, B1) + x1.x;
        o1.y = fmaf(acc[t][3], A1, B1) + x1.y;
        *(float2*)&out[((long)(b * 128 + co0) << 12) + n0 + n] = o0;
        *(float2*)&out[((long)(b * 128 + co1) << 12) + n0 + n] = o1;
    }
}

// ---------------------------------------------------------------------------
extern "C" void kernel_launch(void* const* d_in, const int* in_sizes, int n_in,
                              void* d_out, int out_size) {
    const float* x  = (const float*)d_in[0];
    const float* w1 = (const float*)d_in[1];
    const float* b1 = (const float*)d_in[2];
    const float* w3 = (const float*)d_in[3];
    const float* b3 = (const float*)d_in[4];
    const float* w4 = (const float*)d_in[5];
    const float* b4 = (const float*)d_in[6];
    const float* w5 = (const float*)d_in[7];
    const float* w2 = (const float*)d_in[8];
    const float* b2 = (const float*)d_in[9];
    const float* bg = (const float*)d_in[10];
    const float* bb = (const float*)d_in[11];
    const float* bm = (const float*)d_in[12];
    const float* bv = (const float*)d_in[13];
    float* out = (float*)d_out;

    const int k1_smem = (128 * SWS + 64 * SXS) * 4 + (128 + 64 + 128) * 4;
    const int k3_smem = (8192 + 128 * W2S + 32 * YBS + 1024 + 132 + 64 + 128 + 128 + 256 + 64) * 4;
    cudaFuncSetAttribute(k1_conv, cudaFuncAttributeMaxDynamicSharedMemorySize, k1_smem);
    cudaFuncSetAttribute(k3_out,  cudaFuncAttributeMaxDynamicSharedMemorySize, k3_smem);

    k1_conv<<<dim3(32, 8), 256, k1_smem>>>(x, w1, b1, w4, b4, w5);
    k2_sort<<<8, 1024>>>();
    k2_scan<<<dim3(16, 8), 256>>>();
    k3_out<<<dim3(64, 8), 256, k3_smem>>>(x, w3, b3, w5, w2, b2, bg, bb, bm, bv, out);
}

// round 7
// speedup vs baseline: 3.1834x; 1.0557x over previous
#include <cuda_runtime.h>
#include <cuda_bf16.h>

// B=8, C=128, IC=64, H=W=64, N=4096, M=1024 (pooled 32x32)

__device__ float g_p[8][1024];
__device__ float g_t[8][4096];
__device__ float g_xg[8][1024][64];
__device__ float g_psort[8][1024];
__device__ int   g_perm[8][1024];
__device__ float2 g_S12[8][1025][64];     // interleaved (S1,S2)

// ---- helpers --------------------------------------------------------------
__device__ __forceinline__ unsigned pbf2(float lo, float hi) {
    unsigned r; asm("cvt.rn.bf16x2.f32 %0, %1, %2;" : "=r"(r) : "f"(hi), "f"(lo));
    return r;
}
__device__ __forceinline__ void mma16816(float* d, unsigned a0, unsigned a1,
                                         unsigned a2, unsigned a3,
                                         unsigned b0, unsigned b1) {
    asm("mma.sync.aligned.m16n8k16.row.col.f32.bf16.bf16.f32 "
        "{%0,%1,%2,%3}, {%4,%5,%6,%7}, {%8,%9}, {%0,%1,%2,%3};"
        : "+f"(d[0]), "+f"(d[1]), "+f"(d[2]), "+f"(d[3])
        : "r"(a0), "r"(a1), "r"(a2), "r"(a3), "r"(b0), "r"(b1));
}

// ---------------------------------------------------------------------------
// K1: fused conv1+conv4 via bf16 mma.sync, in-register maxpool,
//     + folded conv3 scalar t (wtp folded per block).
// ---------------------------------------------------------------------------
#define SWS 68
#define SXS 136
__global__ void __launch_bounds__(256, 2)
k1_conv(const float* __restrict__ x,
        const float* __restrict__ w1, const float* __restrict__ b1,
        const float* __restrict__ w3, const float* __restrict__ b3,
        const float* __restrict__ w4, const float* __restrict__ b4,
        const float* __restrict__ w5) {
    extern __shared__ unsigned smu[];
    unsigned* sWb  = smu;                    // 128*68
    unsigned* sXb  = smu + 128 * SWS;        // 64*136
    float* sBias = (float*)(sXb + 64 * SXS); // 128
    float* sWp   = sBias + 128;              // 64
    float* sWtp  = sWp + 64;                 // 132
    float* sPred = sWtp + 132;               // 4*32

    const int tid = threadIdx.x;
    const int pr  = blockIdx.x;
    const int b   = blockIdx.y;

    const float4* w1v = (const float4*)w1;
    const float4* w4v = (const float4*)w4;
    #pragma unroll
    for (int k = 0; k < 16; k++) {
        int v  = tid + k * 256;
        int oc = v >> 5, c4 = v & 31;
        float4 f = (oc < 64) ? w1v[oc * 32 + c4] : w4v[(oc - 64) * 32 + c4];
        *(uint2*)&sWb[oc * SWS + c4 * 2] = make_uint2(pbf2(f.x, f.y), pbf2(f.z, f.w));
    }
    const float4* xv = (const float4*)x;
    #pragma unroll
    for (int it = 0; it < 8; it++) {
        int v   = tid + it * 256;
        int cc  = v >> 5, u = v & 31;
        int r01 = u >> 4, c4 = u & 15;
        float4 fa = xv[((b * 128 + 2 * cc) * 64 + (2 * pr + r01)) * 16 + c4];
        float4 fb = xv[((b * 128 + 2 * cc + 1) * 64 + (2 * pr + r01)) * 16 + c4];
        uint4 q;
        q.x = pbf2(fa.x, fb.x); q.y = pbf2(fa.y, fb.y);
        q.z = pbf2(fa.z, fb.z); q.w = pbf2(fa.w, fb.w);
        *(uint4*)&sXb[cc * SXS + r01 * 64 + c4 * 4] = q;
    }
    // fold wtp = w5[:64]^T w3  (and its bias term)
    if (tid < 128) {
        float acc = 0.f;
        #pragma unroll 16
        for (int i = 0; i < 64; i++) acc = fmaf(w5[i], w3[i * 128 + tid], acc);
        sWtp[tid] = acc;
        sBias[tid] = (tid < 64) ? b1[tid] : b4[tid - 64];
    } else if (tid < 160) {
        int l = tid - 128;
        float s = fmaf(w5[l], b3[l], w5[l + 32] * b3[l + 32]);
        #pragma unroll
        for (int d = 16; d >= 1; d >>= 1)
            s += __shfl_xor_sync(0xffffffffu, s, d);
        if (l == 0) sWtp[128] = s;
    }
    if (tid < 64) sWp[tid] = w5[64 + tid];
    __syncthreads();

    const int w    = tid >> 5;
    const int lane = tid & 31;
    const int g    = lane >> 2;
    const int m4   = lane & 3;
    const int ocb  = w * 16;

    float acc[16][4];
    #pragma unroll
    for (int t = 0; t < 16; t++)
        #pragma unroll
        for (int r = 0; r < 4; r++) acc[t][r] = 0.f;

    #pragma unroll
    for (int s = 0; s < 8; s++) {
        const int cc0 = s * 8;
        unsigned a0 = sWb[(ocb + g)     * SWS + cc0 + m4];
        unsigned a1 = sWb[(ocb + g + 8) * SWS + cc0 + m4];
        unsigned a2 = sWb[(ocb + g)     * SWS + cc0 + 4 + m4];
        unsigned a3 = sWb[(ocb + g + 8) * SWS + cc0 + 4 + m4];
        #pragma unroll
        for (int t = 0; t < 16; t++) {
            unsigned b0 = sXb[(cc0 + m4)     * SXS + t * 8 + g];
            unsigned b1 = sXb[(cc0 + 4 + m4) * SXS + t * 8 + g];
            mma16816(acc[t], a0, a1, a2, a3, b0, b1);
        }
    }

    // t (folded conv3 dot): one pixel per thread for tid<128
    if (tid < 128) {
        float a = sWtp[128];
        #pragma unroll 8
        for (int cc = 0; cc < 64; cc++) {
            unsigned u = sXb[cc * SXS + tid];
            __nv_bfloat162 h = *reinterpret_cast<__nv_bfloat162*>(&u);
            float2 f = __bfloat1622float2(h);
            a = fmaf(sWtp[2 * cc], f.x, a);
            a = fmaf(sWtp[2 * cc + 1], f.y, a);
        }
        int n = (2 * pr + (tid >> 6)) * 64 + (tid & 63);
        g_t[b][n] = a;
    }

    float pg[8], pg8[8];
    #pragma unroll
    for (int t = 0; t < 8; t++) {
        pg[t]  = fmaxf(fmaxf(acc[t][0], acc[t][1]), fmaxf(acc[t + 8][0], acc[t + 8][1]));
        pg8[t] = fmaxf(fmaxf(acc[t][2], acc[t][3]), fmaxf(acc[t + 8][2], acc[t + 8][3]));
    }

    if (w < 4) {  // xg path: oc 0..63
        int oc0 = ocb + g, oc1 = ocb + g + 8;
        float b0v = sBias[oc0], b1v = sBias[oc1];
        #pragma unroll
        for (int t = 0; t < 8; t++) {
            int mb = pr * 32 + t * 4 + m4;
            g_xg[b][mb][oc0] = pg[t]  + b0v;
            g_xg[b][mb][oc1] = pg8[t] + b1v;
        }
    } else {      // p path
        int oc0 = ocb + g, oc1 = ocb + g + 8;
        float wp0 = sWp[oc0 - 64], wp1 = sWp[oc1 - 64];
        float b0v = sBias[oc0], b1v = sBias[oc1];
        float part[8];
        #pragma unroll
        for (int t = 0; t < 8; t++)
            part[t] = fmaf(wp0, pg[t] + b0v, wp1 * (pg8[t] + b1v));
        #pragma unroll
        for (int d = 4; d < 32; d <<= 1) {
            #pragma unroll
            for (int t = 0; t < 8; t++)
                part[t] += __shfl_xor_sync(0xffffffffu, part[t], d);
        }
        if (lane < 4) {
            #pragma unroll
            for (int t = 0; t < 8; t++)
                sPred[(w - 4) * 32 + t * 4 + lane] = part[t];
        }
    }
    __syncthreads();
    if (tid < 32) {
        float pv = sPred[tid] + sPred[32 + tid] + sPred[64 + tid] + sPred[96 + tid];
        g_p[b][pr * 32 + tid] = pv;
    }
}

// ---------------------------------------------------------------------------
// K2a: bitonic sort on packed u64 keys, ping-pong smem
// ---------------------------------------------------------------------------
__global__ void __launch_bounds__(1024) k2_sort() {
    __shared__ unsigned long long skA[1024], skB[1024];
    const int b = blockIdx.x, tid = threadIdx.x;
    float v = g_p[b][tid];
    unsigned u = __float_as_uint(v);
    u = (u & 0x80000000u) ? ~u : (u | 0x80000000u);
    unsigned long long key = ((unsigned long long)u << 32) | (unsigned)tid;

    int pb = 0;
    #pragma unroll
    for (int k = 2; k <= 1024; k <<= 1) {
        const bool up = ((tid & k) == 0);
        for (int j = k >> 1; j >= 32; j >>= 1) {
            unsigned long long* buf = pb ? skB : skA;
            buf[tid] = key;
            __syncthreads();
            unsigned long long ok = buf[tid ^ j];
            pb ^= 1;
            bool takeMin = (((tid & j) == 0) == up);
            if ((key > ok) == takeMin) key = ok;
        }
        #pragma unroll
        for (int j = ((k >> 1) < 16 ? (k >> 1) : 16); j >= 1; j >>= 1) {
            unsigned long long ok = __shfl_xor_sync(0xffffffffu, key, j);
            bool takeMin = (((tid & j) == 0) == up);
            if ((key > ok) == takeMin) key = ok;
        }
    }
    int m = (int)(key & 1023u);
    g_perm[b][tid]  = m;
    g_psort[b][tid] = g_p[b][m];
}

// ---------------------------------------------------------------------------
// K2b: suffix scan, 256 threads x 4 consecutive j x 4 channels.
// ---------------------------------------------------------------------------
__global__ void __launch_bounds__(256) k2_scan() {
    __shared__ float sm1[4][8], sm2[4][8];
    const int b = blockIdx.y, ig = blockIdx.x;
    const int tid = threadIdx.x, lane = tid & 31, w = tid >> 5;
    const int j0 = 4 * tid;

    if (tid == 0) {
        float2* z = &g_S12[b][1024][ig * 4];
        *(float4*)z       = make_float4(0.f, 0.f, 0.f, 0.f);
        *(float4*)(z + 2) = make_float4(0.f, 0.f, 0.f, 0.f);
    }

    const int4   pm = ((const int4*)g_perm[b])[tid];
    const float4 ps = ((const float4*)g_psort[b])[tid];

    float4 v0 = *(const float4*)&g_xg[b][pm.x][ig * 4];
    float4 v1 = *(const float4*)&g_xg[b][pm.y][ig * 4];
    float4 v2 = *(const float4*)&g_xg[b][pm.z][ig * 4];
    float4 v3 = *(const float4*)&g_xg[b][pm.w][ig * 4];
    float vv[4][4] = {{v0.x, v0.y, v0.z, v0.w}, {v1.x, v1.y, v1.z, v1.w},
                      {v2.x, v2.y, v2.z, v2.w}, {v3.x, v3.y, v3.z, v3.w}};
    float pp[4] = {ps.x, ps.y, ps.z, ps.w};

    float s1[4], s2[4];
    #pragma unroll
    for (int c = 0; c < 4; c++) {
        s1[c] = vv[0][c] + vv[1][c] + vv[2][c] + vv[3][c];
        s2[c] = fmaf(pp[0], vv[0][c], fmaf(pp[1], vv[1][c],
                fmaf(pp[2], vv[2][c], pp[3] * vv[3][c])));
    }

    #pragma unroll
    for (int d = 1; d < 32; d <<= 1) {
        bool take = (lane + d < 32);
        #pragma unroll
        for (int c = 0; c < 4; c++) {
            float t1 = __shfl_down_sync(0xffffffffu, s1[c], d);
            float t2 = __shfl_down_sync(0xffffffffu, s2[c], d);
            if (take) { s1[c] += t1; s2[c] += t2; }
        }
    }
    if (lane == 0) {
        #pragma unroll
        for (int c = 0; c < 4; c++) { sm1[c][w] = s1[c]; sm2[c][w] = s2[c]; }
    }
    __syncthreads();
    #pragma unroll
    for (int c = 0; c < 4; c++) {
        float c1 = 0.f, c2 = 0.f;
        #pragma unroll
        for (int w2 = 0; w2 < 8; w2++)
            if (w2 > w) { c1 += sm1[c][w2]; c2 += sm2[c][w2]; }
        s1[c] += c1; s2[c] += c2;
    }

    float2* base = &g_S12[b][j0][ig * 4];
    #pragma unroll
    for (int k = 0; k < 4; k++) {
        float4 oa = make_float4(s1[0], s2[0], s1[1], s2[1]);
        float4 ob = make_float4(s1[2], s2[2], s1[3], s2[3]);
        float2* dst = base + (long)k * 64;
        *(float4*)dst       = oa;
        *(float4*)(dst + 2) = ob;
        if (k < 3) {
            #pragma unroll
            for (int c = 0; c < 4; c++) {
                s1[c] -= vv[k][c];
                s2[c] = fmaf(-pp[k], vv[k][c], s2[c]);
            }
        }
    }
}

// ---------------------------------------------------------------------------
// K3: slim — psort+w2 stage, inline binsearch, y packed bf16,
//     conv2 via bf16 mma.sync, BN + residual with direct gmem x reads.
// grid (64 tiles, 8 batch), 256 threads, smem ~33KB
// ---------------------------------------------------------------------------
#define W2S 36
#define YBS 68
__global__ void __launch_bounds__(256)
k3_out(const float* __restrict__ x, const float* __restrict__ w2,
       const float* __restrict__ b2,
       const float* __restrict__ bg, const float* __restrict__ bb,
       const float* __restrict__ bm, const float* __restrict__ bv,
       float* __restrict__ out) {
    extern __shared__ float sm[];
    unsigned* sW2b = (unsigned*)sm;              // 128*36
    unsigned* sYb  = sW2b + 128 * W2S;           // 32*68
    float*    sPs  = (float*)(sYb + 32 * YBS);   // 1024
    float*    sT   = sPs + 1024;                 // 64
    float*    sA   = sT + 64;                    // 128
    float*    sB   = sA + 128;                   // 128

    const int tid = threadIdx.x;
    const int tile = blockIdx.x, b = blockIdx.y;
    const int n0 = tile * 64;

    // pack w2 (f32 -> bf16x2), re-strided to 36
    const float4* w2v = (const float4*)w2;
    #pragma unroll
    for (int k = 0; k < 8; k++) {
        int v = tid + k * 256;
        int co = v >> 4, q4 = v & 15;
        float4 f = w2v[v];
        *(uint2*)&sW2b[co * W2S + q4 * 2] = make_uint2(pbf2(f.x, f.y), pbf2(f.z, f.w));
    }
    ((float4*)sPs)[tid] = ((const float4*)g_psort[b])[tid];
    if (tid < 64) sT[tid] = g_t[b][n0 + tid];
    if (tid >= 128) {
        int c = tid - 128;
        float inv = rsqrtf(bv[c] + 1e-5f);
        float al  = bg[c] * inv;
        sA[c] = al;
        sB[c] = (b2[c] - bm[c]) * al + bb[c];
    }
    __syncthreads();

    // y build with inline binary search (4 threads per pixel, redundant search)
    {
        int n = tid >> 2, q = tid & 3;
        float t = sT[n];
        float key = -t;
        int lo = 0, hi = 1024;
        while (lo < hi) { int mid = (lo + hi) >> 1; if (sPs[mid] > key) hi = mid; else lo = mid + 1; }
        const float4* s4 = (const float4*)&g_S12[b][lo][q * 16];
        #pragma unroll
        for (int r = 0; r < 8; r++) {
            float4 s = s4[r];
            float y0 = fmaf(t, s.x, s.y) * (1.0f / 1024.0f);
            float y1 = fmaf(t, s.z, s.w) * (1.0f / 1024.0f);
            sYb[(q * 8 + r) * YBS + n] = pbf2(y0, y1);
        }
    }
    __syncthreads();

    const int w    = tid >> 5;
    const int lane = tid & 31;
    const int g    = lane >> 2;
    const int m4   = lane & 3;
    const int ocb  = w * 16;

    float acc[8][4];
    #pragma unroll
    for (int t = 0; t < 8; t++)
        #pragma unroll
        for (int r = 0; r < 4; r++) acc[t][r] = 0.f;

    #pragma unroll
    for (int s = 0; s < 4; s++) {
        const int ii0 = s * 8;
        unsigned a0 = sW2b[(ocb + g)     * W2S + ii0 + m4];
        unsigned a1 = sW2b[(ocb + g + 8) * W2S + ii0 + m4];
        unsigned a2 = sW2b[(ocb + g)     * W2S + ii0 + 4 + m4];
        unsigned a3 = sW2b[(ocb + g + 8) * W2S + ii0 + 4 + m4];
        #pragma unroll
        for (int t = 0; t < 8; t++) {
            unsigned b0 = sYb[(ii0 + m4)     * YBS + t * 8 + g];
            unsigned b1 = sYb[(ii0 + 4 + m4) * YBS + t * 8 + g];
            mma16816(acc[t], a0, a1, a2, a3, b0, b1);
        }
    }

    // epilogue: BN + residual (x read directly from gmem, L2-resident)
    const int co0 = ocb + g, co1 = ocb + g + 8;
    const float A0 = sA[co0], B0 = sB[co0];
    const float A1 = sA[co1], B1 = sB[co1];
    const long base0 = ((long)(b * 128 + co0) << 12) + n0;
    const long base1 = ((long)(b * 128 + co1) << 12) + n0;
    #pragma unroll
    for (int t = 0; t < 8; t++) {
        int n = t * 8 + 2 * m4;
        float2 x0 = *(const float2*)&x[base0 + n];
        float2 x1 = *(const float2*)&x[base1 + n];
        float2 o0, o1;
        o0.x = fmaf(acc[t][0], A0, B0) + x0.x;
        o0.y = fmaf(acc[t][1], A0, B0) + x0.y;
        o1.x = fmaf(acc[t][2], A1, B1) + x1.x;
        o1.y = fmaf(acc[t][3], A1, B1) + x1.y;
        *(float2*)&out[base0 + n] = o0;
        *(float2*)&out[base1 + n] = o1;
    }
}

// ---------------------------------------------------------------------------
extern "C" void kernel_launch(void* const* d_in, const int* in_sizes, int n_in,
                              void* d_out, int out_size) {
    const float* x  = (const float*)d_in[0];
    const float* w1 = (const float*)d_in[1];
    const float* b1 = (const float*)d_in[2];
    const float* w3 = (const float*)d_in[3];
    const float* b3 = (const float*)d_in[4];
    const float* w4 = (const float*)d_in[5];
    const float* b4 = (const float*)d_in[6];
    const float* w5 = (const float*)d_in[7];
    const float* w2 = (const float*)d_in[8];
    const float* b2 = (const float*)d_in[9];
    const float* bg = (const float*)d_in[10];
    const float* bb = (const float*)d_in[11];
    const float* bm = (const float*)d_in[12];
    const float* bv = (const float*)d_in[13];
    float* out = (float*)d_out;

    const int k1_smem = (128 * SWS + 64 * SXS) * 4 + (128 + 64 + 132 + 128) * 4;
    const int k3_smem = (128 * W2S + 32 * YBS) * 4 + (1024 + 64 + 128 + 128) * 4;
    cudaFuncSetAttribute(k1_conv, cudaFuncAttributeMaxDynamicSharedMemorySize, k1_smem);
    cudaFuncSetAttribute(k3_out,  cudaFuncAttributeMaxDynamicSharedMemorySize, k3_smem);

    k1_conv<<<dim3(32, 8), 256, k1_smem>>>(x, w1, b1, w3, b3, w4, b4, w5);
    k2_sort<<<8, 1024>>>();
    k2_scan<<<dim3(16, 8), 256>>>();
    k3_out<<<dim3(64, 8), 256, k3_smem>>>(x, w2, b2, bg, bb, bm, bv, out);
}